// round 11
// baseline (speedup 1.0000x reference)
#include <cuda_runtime.h>
#include <cuda_fp16.h>
#include <math.h>
#include <stdint.h>

#define Bc   32
#define DIM  256
#define Hc   56
#define Wc   56
#define HWc  (Hc*Wc)          // 3136
#define TOK  (Bc*HWc)         // 100352
#define HID  1024

typedef __half f16;

// ---------------- scratch (device globals; no runtime allocation) ------------
__device__ __align__(256) f16 g_conv[(size_t)Bc*DIM*HWc];    // conv out, NCHW f16
__device__ __align__(256) f16 g_a  [(size_t)TOK*DIM];        // LN out (fp16)
__device__ __align__(256) f16 g_h  [(size_t)TOK*HID];        // hidden (fp16)
__device__ __align__(256) f16 g_w1t[(size_t)HID*DIM];        // w1^T [N=1024][K=256]
__device__ __align__(256) f16 g_w2t[(size_t)DIM*HID];        // w2^T [N=256][K=1024]

// ---------------- asm primitives (base sm_103, no 'a' features) --------------
__device__ __forceinline__ uint32_t smem_u32(const void* p) {
    uint32_t a;
    asm("{ .reg .u64 t; cvta.to.shared.u64 t, %1; cvt.u32.u64 %0, t; }"
        : "=r"(a) : "l"(p));
    return a;
}
#define CP16(dst, src) \
    asm volatile("cp.async.cg.shared.global [%0], [%1], 16;" \
                 :: "r"(dst), "l"(src) : "memory")
#define CP_COMMIT() asm volatile("cp.async.commit_group;" ::: "memory")
#define CP_WAIT(n)  asm volatile("cp.async.wait_group %0;" :: "n"(n) : "memory")
#define LDSM4(r, addr) \
    asm volatile("ldmatrix.sync.aligned.m8n8.x4.shared.b16 {%0,%1,%2,%3}, [%4];" \
                 : "=r"((r)[0]), "=r"((r)[1]), "=r"((r)[2]), "=r"((r)[3]) \
                 : "r"(addr))
#define MMA16816(d, a, b0v, b1v) \
    asm volatile("mma.sync.aligned.m16n8k16.row.col.f32.f16.f16.f32 " \
                 "{%0,%1,%2,%3}, {%4,%5,%6,%7}, {%8,%9}, {%0,%1,%2,%3};" \
                 : "+f"((d)[0]), "+f"((d)[1]), "+f"((d)[2]), "+f"((d)[3]) \
                 : "r"((a)[0]), "r"((a)[1]), "r"((a)[2]), "r"((a)[3]), \
                   "r"(b0v), "r"(b1v))

__device__ __forceinline__ uint32_t sw128(uint32_t off) {
    return off ^ ((off >> 3) & 0x70);
}
__device__ __forceinline__ uint32_t pack2(f16 a, f16 b) {
    return (uint32_t)*(uint16_t*)&a | ((uint32_t)*(uint16_t*)&b << 16);
}

// Fast exact-GELU: Abramowitz-Stegun 7.1.26 erf (|abs err| <= 1.5e-7).
__device__ __forceinline__ float gelu_fast(float x) {
    const float t = fabsf(x) * 0.70710678118654752f;
    const float u = __fdividef(1.f, fmaf(0.3275911f, t, 1.f));
    float p = fmaf(1.061405429f, u, -1.453152027f);
    p = fmaf(p, u, 1.421413741f);
    p = fmaf(p, u, -0.284496736f);
    p = fmaf(p, u, 0.254829592f);
    p = p * u;
    const float e  = __expf(-t * t);
    const float er = copysignf(fmaf(-p, e, 1.f), x);
    return 0.5f * x * (1.f + er);
}

// ------- 1) depthwise 7x7 conv + bias: sliding-window registers --------------
// One block per (b,c) plane. Each thread owns one column and 14 consecutive
// rows, keeping the 7x7 input window + all 49 weights in registers: only 7
// new smem loads per output (was 49).
__global__ __launch_bounds__(256, 2) void dwconv_kernel(
    const float* __restrict__ x, const float* __restrict__ cw,
    const float* __restrict__ cb)
{
    const int bc = blockIdx.x;            // b*DIM + c
    const int c  = bc & (DIM-1);

    __shared__ float sx[62][64];          // rows -3..58, cols -3..60 (pad 64)
    __shared__ float swm[49];

    const float* xp = x + (size_t)bc*HWc;
    const int t = threadIdx.x;
    if (t < 49) swm[t] = cw[c*49 + t];

    for (int i = t; i < 62*64; i += 256) {
        const int r = i >> 6, col = i & 63;
        const int gr = r - 3, gc = col - 3;
        float v = 0.f;
        if (gr >= 0 && gr < Hc && gc >= 0 && gc < Wc)
            v = xp[gr*Wc + gc];
        sx[r][col] = v;
    }
    __syncthreads();

    const int col = t & 63, q = t >> 6;   // column, row-quarter (14 rows each)
    if (col < Wc) {
        float w[49];
        #pragma unroll
        for (int i = 0; i < 49; i++) w[i] = swm[i];
        const float bias = cb[c];

        const int r0 = q * 14;            // output row base (= sx row base)
        float win[7][7];
        #pragma unroll
        for (int r = 0; r < 6; r++)
            #pragma unroll
            for (int kj = 0; kj < 7; kj++)
                win[r][kj] = sx[r0 + r][col + kj];

        f16* op = g_conv + (size_t)bc*HWc;
        #pragma unroll
        for (int rr = 0; rr < 14; rr++) {
            const int wr = (rr + 6) % 7;  // rotate: load newest row
            #pragma unroll
            for (int kj = 0; kj < 7; kj++)
                win[wr][kj] = sx[r0 + rr + 6][col + kj];
            float acc = bias;
            #pragma unroll
            for (int ki = 0; ki < 7; ki++) {
                const int r = (rr + ki) % 7;
                #pragma unroll
                for (int kj = 0; kj < 7; kj++)
                    acc = fmaf(win[r][kj], w[ki*7 + kj], acc);
            }
            op[(r0 + rr)*Wc + col] = __float2half_rn(acc);
        }
    }
}

// ------- 2) LayerNorm: 64-pixel tiles, half2 full-width loads -----------------
__global__ __launch_bounds__(256) void ln_kernel(
    const float* __restrict__ gamma, const float* __restrict__ beta)
{
    const int tile = blockIdx.x;                  // 64 pixels per block
    const int b    = tile / (HWc/64);
    const int pixbase = (tile % (HWc/64)) * 64;

    __shared__ uint32_t s2[DIM][33];              // half2: pixels (2p, 2p+1)
    __shared__ float ps0[8][32], ps1[8][32], pq0[8][32], pq1[8][32];
    __shared__ float mu_s[64], rs_s[64];
    __shared__ float sg[DIM], sbt[DIM];

    const int t = threadIdx.x;
    const int p = t & 31, gi = t >> 5;
    sg[t]  = gamma[t];
    sbt[t] = beta[t];

    const f16* base = g_conv + (size_t)b*DIM*HWc + pixbase;
    float s0 = 0.f, s1 = 0.f, q0 = 0.f, q1 = 0.f;
    #pragma unroll
    for (int cc = 0; cc < 32; cc++) {
        const int c = gi*32 + cc;
        const uint32_t v = *(const uint32_t*)(base + (size_t)c*HWc + 2*p);
        s2[c][p] = v;
        const __half2 h2 = *(const __half2*)&v;
        const float f0 = __low2float(h2), f1 = __high2float(h2);
        s0 += f0; q0 = fmaf(f0, f0, q0);
        s1 += f1; q1 = fmaf(f1, f1, q1);
    }
    ps0[gi][p] = s0; ps1[gi][p] = s1;
    pq0[gi][p] = q0; pq1[gi][p] = q1;
    __syncthreads();

    if (gi == 0) {
        float S0 = 0.f, S1 = 0.f, Q0 = 0.f, Q1 = 0.f;
        #pragma unroll
        for (int k = 0; k < 8; k++) {
            S0 += ps0[k][p]; S1 += ps1[k][p];
            Q0 += pq0[k][p]; Q1 += pq1[k][p];
        }
        const float mu0 = S0 * (1.f/DIM), mu1 = S1 * (1.f/DIM);
        mu_s[2*p    ] = mu0; rs_s[2*p    ] = rsqrtf(Q0*(1.f/DIM) - mu0*mu0 + 1e-6f);
        mu_s[2*p + 1] = mu1; rs_s[2*p + 1] = rsqrtf(Q1*(1.f/DIM) - mu1*mu1 + 1e-6f);
    }
    __syncthreads();

    const size_t tokbase = (size_t)b*HWc + pixbase;
    for (int i = t; i < 64*128; i += 256) {
        const int pp = i >> 7, c2 = (i & 127) * 2;
        const uint32_t v0 = s2[c2][pp >> 1], v1 = s2[c2 + 1][pp >> 1];
        const __half2 h0 = *(const __half2*)&v0, h1 = *(const __half2*)&v1;
        const float f0 = (pp & 1) ? __high2float(h0) : __low2float(h0);
        const float f1 = (pp & 1) ? __high2float(h1) : __low2float(h1);
        const float mu = mu_s[pp], rs = rs_s[pp];
        const float o0 = (f0 - mu) * rs * sg[c2    ] + sbt[c2    ];
        const float o1 = (f1 - mu) * rs * sg[c2 + 1] + sbt[c2 + 1];
        *(uint32_t*)(g_a + (tokbase + pp)*DIM + c2) =
            pack2(__float2half_rn(o0), __float2half_rn(o1));
    }
}

// ------- 2b) transpose weights to fp16: w1[K,N]->w1t[N,K], w2 likewise -------
__global__ __launch_bounds__(256) void prep_w_kernel(
    const float* __restrict__ w1, const float* __restrict__ w2)
{
    int idx = blockIdx.x * 256 + threadIdx.x;
    if (idx < HID*DIM) {                       // w1t [n=1024][k=256]
        int n = idx >> 8, k = idx & 255;
        g_w1t[idx] = __float2half_rn(w1[(size_t)k*HID + n]);
    } else {                                   // w2t [n=256][k=1024]
        int j = idx - HID*DIM;
        int n = j >> 10, k = j & 1023;
        g_w2t[j] = __float2half_rn(w2[(size_t)k*DIM + n]);
    }
}

// ---------------- 3/4) HMMA fp16 GEMM (unchanged from R10, ~HW ceiling) ------
#define STAGE  32768
#define GSMEM  (3*STAGE)     // 98304

#define LDSMA(dst, base) do {            \
    LDSM4((dst)[0], (base));             \
    LDSM4((dst)[1], (base) + 2048);      \
    LDSM4((dst)[2], (base) + 4096);      \
    LDSM4((dst)[3], (base) + 6144); } while (0)
#define LDSMB(dst, base) do {            \
    uint32_t _r[4];                      \
    LDSM4(_r, (base));                   \
    (dst)[0][0]=_r[0]; (dst)[0][1]=_r[1]; (dst)[1][0]=_r[2]; (dst)[1][1]=_r[3]; \
    LDSM4(_r, (base) + 2048);            \
    (dst)[2][0]=_r[0]; (dst)[2][1]=_r[1]; (dst)[3][0]=_r[2]; (dst)[3][1]=_r[3]; } while (0)

template<int KTOT, int MODE>
__global__ __launch_bounds__(256, 2) void hgemm_kernel(
    const f16* __restrict__ A, const f16* __restrict__ Bw,
    const float* __restrict__ bias,
    f16* __restrict__ Oh, float* __restrict__ Of)
{
    extern __shared__ char smem[];
    __shared__ float sbias[128];

    const int tid  = threadIdx.x;
    const int wid  = tid >> 5, lane = tid & 31;
    const int warpM = wid >> 2, warpN = wid & 3;        // 2 x 4
    const int n0 = blockIdx.x * 128;
    const size_t m0 = (size_t)blockIdx.y * 128;

    if (tid < 128) sbias[tid] = bias[n0 + tid];

    const uint32_t sb = smem_u32(smem);

    const f16* Abase = A + m0 * KTOT;
    const f16* Bbase = Bw + (size_t)n0 * KTOT;
    const uint32_t soff0 = sw128((uint32_t)((tid >> 3)*128 + (tid & 7)*16));
    const uint32_t goff0 = (uint32_t)(tid >> 3) * (uint32_t)KTOT + (tid & 7)*8;

    auto load_stage = [&](int c, int s) {
        const uint32_t st = sb + s * STAGE + soff0;
        const f16* ga = Abase + goff0 + (uint32_t)c * 64;
        const f16* gb = Bbase + goff0 + (uint32_t)c * 64;
        #pragma unroll
        for (int it = 0; it < 4; it++) {
            CP16(st + it*4096,         ga + it*32*KTOT);
            CP16(st + 16384 + it*4096, gb + it*32*KTOT);
        }
    };

    const int j  = lane >> 3, lr = lane & 7;
    const uint32_t mask = (uint32_t)lr << 4;
    const uint32_t aoff0 = (uint32_t)(warpM*64 + ((j & 1) << 3) + lr)*128
                         + (((uint32_t)(j >> 1) << 4) ^ mask);
    const uint32_t boff0 = 16384
                         + (uint32_t)(warpN*32 + ((j >> 1) << 3) + lr)*128
                         + (((uint32_t)(j & 1) << 4) ^ mask);

    float acc[4][4][4] = {};
    uint32_t ah[2][4][4], bh[2][4][2];

    const int NC = KTOT / 64;
    load_stage(0, 0); CP_COMMIT();
    if (NC > 1) { load_stage(1, 1); CP_COMMIT(); }

    int s_use = 0, s_load = 2;
    #pragma unroll 1
    for (int c = 0; c < NC; c++) {
        if (c + 1 < NC) { CP_WAIT(1); } else { CP_WAIT(0); }
        __syncthreads();

        const uint32_t st = sb + s_use * STAGE;
        if (++s_use == 3) s_use = 0;
        const uint32_t a0 = st + aoff0, b0 = st + boff0;

        LDSMB(bh[0], b0);
        LDSMA(ah[0], a0);
        if (c + 2 < NC) {
            load_stage(c + 2, s_load); CP_COMMIT();
            if (++s_load == 3) s_load = 0;
        }

        #pragma unroll
        for (int ks = 0; ks < 4; ks++) {
            const int cur = ks & 1, nxt = cur ^ 1;
            if (ks < 3) {
                const uint32_t kx = 32u * (ks + 1);
                LDSMB(bh[nxt], b0 ^ kx);
                LDSMA(ah[nxt], a0 ^ kx);
            }
            #pragma unroll
            for (int mt = 0; mt < 4; mt++)
                #pragma unroll
                for (int nt = 0; nt < 4; nt++)
                    MMA16816(acc[mt][nt], ah[cur][mt],
                             bh[cur][nt][0], bh[cur][nt][1]);
        }
    }

    const int mlane = lane >> 2;
    const int nlane = (lane & 3) * 2;

    if (MODE == 1) {
        #pragma unroll
        for (int mt = 0; mt < 4; mt++) {
            const size_t mA = m0 + warpM*64 + mt*16 + mlane;
            #pragma unroll
            for (int nt = 0; nt < 4; nt++) {
                const int nc = warpN*32 + nt*8 + nlane;
                const float b0 = sbias[nc], b1 = sbias[nc + 1];
                #pragma unroll
                for (int half = 0; half < 2; half++) {
                    float v0 = gelu_fast(acc[mt][nt][half*2]     + b0);
                    float v1 = gelu_fast(acc[mt][nt][half*2 + 1] + b1);
                    size_t o = (mA + half*8) * (size_t)HID + n0 + nc;
                    *(uint32_t*)(Oh + o) = pack2(__float2half_rn(v0),
                                                 __float2half_rn(v1));
                }
            }
        }
    } else {
        __syncthreads();
        float* sf = (float*)smem;          // [128 n][132 m]
        #pragma unroll
        for (int mt = 0; mt < 4; mt++) {
            const int mA = warpM*64 + mt*16 + mlane;
            #pragma unroll
            for (int nt = 0; nt < 4; nt++) {
                const int nc = warpN*32 + nt*8 + nlane;
                sf[(nc    )*132 + mA    ] = acc[mt][nt][0];
                sf[(nc + 1)*132 + mA    ] = acc[mt][nt][1];
                sf[(nc    )*132 + mA + 8] = acc[mt][nt][2];
                sf[(nc + 1)*132 + mA + 8] = acc[mt][nt][3];
            }
        }
        __syncthreads();
        #pragma unroll 4
        for (int i = tid; i < 128*128; i += 256) {
            const int n = i >> 7, mm = i & 127;
            const int tok = (int)m0 + mm;
            const int b = tok / HWc, pix = tok % HWc;
            Of[((size_t)b*DIM + n0 + n)*HWc + pix] = sf[n*132 + mm] + sbias[n];
        }
    }
}

// ---------------- launch -----------------------------------------------------
extern "C" void kernel_launch(void* const* d_in, const int* in_sizes, int n_in,
                              void* d_out, int out_size)
{
    const float* x      = (const float*)d_in[0];
    const float* conv_w = (const float*)d_in[1];
    const float* conv_b = (const float*)d_in[2];
    const float* ln_g   = (const float*)d_in[3];
    const float* ln_b   = (const float*)d_in[4];
    const float* w1     = (const float*)d_in[5];
    const float* b1     = (const float*)d_in[6];
    const float* w2     = (const float*)d_in[7];
    const float* b2     = (const float*)d_in[8];
    float* out = (float*)d_out;

    f16 *p_a, *p_h, *p_w1t, *p_w2t;
    cudaGetSymbolAddress((void**)&p_a,   g_a);
    cudaGetSymbolAddress((void**)&p_h,   g_h);
    cudaGetSymbolAddress((void**)&p_w1t, g_w1t);
    cudaGetSymbolAddress((void**)&p_w2t, g_w2t);

    cudaFuncSetAttribute((const void*)hgemm_kernel<DIM, 1>,
                         cudaFuncAttributeMaxDynamicSharedMemorySize, GSMEM);
    cudaFuncSetAttribute((const void*)hgemm_kernel<HID, 2>,
                         cudaFuncAttributeMaxDynamicSharedMemorySize, GSMEM);

    dwconv_kernel<<<Bc*DIM, 256>>>(x, conv_w, conv_b);
    ln_kernel<<<TOK/64, 256>>>(ln_g, ln_b);
    prep_w_kernel<<<(2*HID*DIM)/256, 256>>>(w1, w2);

    // GEMM1: [TOK,256] x w1t -> GELU -> h (fp16)
    hgemm_kernel<DIM, 1><<<dim3(HID/128, TOK/128), 256, GSMEM>>>(
        p_a, p_w1t, b1, p_h, nullptr);
    // GEMM2: [TOK,1024] x w2t -> +b2 -> fp32 NCHW out
    hgemm_kernel<HID, 2><<<dim3(DIM/128, TOK/128), 256, GSMEM>>>(
        p_h, p_w2t, b2, nullptr, out);
}

// round 12
// speedup vs baseline: 1.0217x; 1.0217x over previous
#include <cuda_runtime.h>
#include <cuda_fp16.h>
#include <math.h>
#include <stdint.h>

#define Bc   32
#define DIM  256
#define Hc   56
#define Wc   56
#define HWc  (Hc*Wc)          // 3136
#define TOK  (Bc*HWc)         // 100352
#define HID  1024

typedef __half f16;

// ---------------- scratch (device globals; no runtime allocation) ------------
__device__ __align__(256) f16 g_conv[(size_t)Bc*DIM*HWc];    // conv out, NCHW f16
__device__ __align__(256) f16 g_a  [(size_t)TOK*DIM];        // LN out (fp16)
__device__ __align__(256) f16 g_h  [(size_t)TOK*HID];        // hidden (fp16)
__device__ __align__(256) f16 g_w1t[(size_t)HID*DIM];        // w1^T [N=1024][K=256]
__device__ __align__(256) f16 g_w2t[(size_t)DIM*HID];        // w2^T [N=256][K=1024]

// ---------------- asm primitives (base sm_103, no 'a' features) --------------
__device__ __forceinline__ uint32_t smem_u32(const void* p) {
    uint32_t a;
    asm("{ .reg .u64 t; cvta.to.shared.u64 t, %1; cvt.u32.u64 %0, t; }"
        : "=r"(a) : "l"(p));
    return a;
}
#define CP16(dst, src) \
    asm volatile("cp.async.cg.shared.global [%0], [%1], 16;" \
                 :: "r"(dst), "l"(src) : "memory")
#define CP_COMMIT() asm volatile("cp.async.commit_group;" ::: "memory")
#define CP_WAIT(n)  asm volatile("cp.async.wait_group %0;" :: "n"(n) : "memory")
#define LDSM4(r, addr) \
    asm volatile("ldmatrix.sync.aligned.m8n8.x4.shared.b16 {%0,%1,%2,%3}, [%4];" \
                 : "=r"((r)[0]), "=r"((r)[1]), "=r"((r)[2]), "=r"((r)[3]) \
                 : "r"(addr))
#define MMA16816(d, a, b0v, b1v) \
    asm volatile("mma.sync.aligned.m16n8k16.row.col.f32.f16.f16.f32 " \
                 "{%0,%1,%2,%3}, {%4,%5,%6,%7}, {%8,%9}, {%0,%1,%2,%3};" \
                 : "+f"((d)[0]), "+f"((d)[1]), "+f"((d)[2]), "+f"((d)[3]) \
                 : "r"((a)[0]), "r"((a)[1]), "r"((a)[2]), "r"((a)[3]), \
                   "r"(b0v), "r"(b1v))

__device__ __forceinline__ uint32_t sw128(uint32_t off) {
    return off ^ ((off >> 3) & 0x70);
}
__device__ __forceinline__ uint32_t pack2(f16 a, f16 b) {
    return (uint32_t)*(uint16_t*)&a | ((uint32_t)*(uint16_t*)&b << 16);
}

// Fast exact-GELU: Abramowitz-Stegun 7.1.26 erf (|abs err| <= 1.5e-7).
__device__ __forceinline__ float gelu_fast(float x) {
    const float t = fabsf(x) * 0.70710678118654752f;
    const float u = __fdividef(1.f, fmaf(0.3275911f, t, 1.f));
    float p = fmaf(1.061405429f, u, -1.453152027f);
    p = fmaf(p, u, 1.421413741f);
    p = fmaf(p, u, -0.284496736f);
    p = fmaf(p, u, 0.254829592f);
    p = p * u;
    const float e  = __expf(-t * t);
    const float er = copysignf(fmaf(-p, e, 1.f), x);
    return 0.5f * x * (1.f + er);
}

// ------- 1) depthwise 7x7 conv + bias: 7x4 output patches --------------------
// 2 planes per 224-thread block; each thread owns a 7-row x 4-col patch
// (112 patches/plane, 14 col-groups x 8 row-groups; 56 = 8*7 = 14*4 exact).
// Window streamed from smem: 13x10 loads per 28 outputs (4.6 LDS/output vs 98),
// weights in registers, FMA-floor bound.
__global__ __launch_bounds__(224) void dwconv_kernel(
    const float* __restrict__ x, const float* __restrict__ cw,
    const float* __restrict__ cb)
{
    const int t  = threadIdx.x;
    const int pl = t / 112;               // plane within block (0/1)
    const int pt = t % 112;               // patch id
    const int pc = pt % 14, pr = pt / 14; // col-group (4 cols), row-group (7 rows)
    const int bc = blockIdx.x * 2 + pl;   // global (b,c) plane
    const int c  = bc & (DIM-1);

    __shared__ float sx[2][62][65];       // rows -3..58, cols -3..60 (pad 65)
    __shared__ float sw[2][49];

    if (t < 98) {
        const int p2 = t / 49, k = t % 49;
        const int cc = (blockIdx.x*2 + p2) & (DIM-1);
        sw[p2][k] = cw[cc*49 + k];
    }

    const float* xp0 = x + (size_t)(blockIdx.x*2)*HWc;
    for (int i = t; i < 62*64; i += 224) {
        const int r = i >> 6, col = i & 63;
        const int gr = r - 3, gc = col - 3;
        const bool ok = (gr >= 0 && gr < Hc && gc >= 0 && gc < Wc);
        sx[0][r][col] = ok ? xp0[gr*Wc + gc] : 0.f;
        sx[1][r][col] = ok ? xp0[HWc + gr*Wc + gc] : 0.f;
    }
    __syncthreads();

    float w[49];
    #pragma unroll
    for (int i = 0; i < 49; i++) w[i] = sw[pl][i];
    const float bias = cb[c];

    const int r0 = pr * 7, c0 = pc * 4;
    float acc[7][4];
    #pragma unroll
    for (int r = 0; r < 7; r++)
        #pragma unroll
        for (int cx = 0; cx < 4; cx++) acc[r][cx] = bias;

    #pragma unroll
    for (int wr = 0; wr < 13; wr++) {
        #pragma unroll
        for (int wc = 0; wc < 10; wc++) {
            const float v = sx[pl][r0 + wr][c0 + wc];
            #pragma unroll
            for (int r = 0; r < 7; r++) {
                if (wr - r >= 0 && wr - r < 7) {
                    #pragma unroll
                    for (int cx = 0; cx < 4; cx++) {
                        if (wc - cx >= 0 && wc - cx < 7)
                            acc[r][cx] = fmaf(v, w[(wr - r)*7 + (wc - cx)],
                                              acc[r][cx]);
                    }
                }
            }
        }
    }

    f16* op = g_conv + (size_t)bc*HWc + r0*Wc + c0;
    #pragma unroll
    for (int r = 0; r < 7; r++) {
        uint2 pv;
        pv.x = pack2(__float2half_rn(acc[r][0]), __float2half_rn(acc[r][1]));
        pv.y = pack2(__float2half_rn(acc[r][2]), __float2half_rn(acc[r][3]));
        *(uint2*)(op + r*Wc) = pv;
    }
}

// ------- 2) LayerNorm over channels + NCHW->NHWC, emit fp16 (R9/R10 exact) ---
__global__ __launch_bounds__(256) void ln_kernel(
    const float* __restrict__ gamma, const float* __restrict__ beta)
{
    int tile = blockIdx.x;
    int b    = tile / (HWc/32);
    int pixbase = (tile % (HWc/32)) * 32;

    __shared__ float s[DIM][33];
    __shared__ float psum[8][32], psq[8][32];
    __shared__ float mu_s[32], rs_s[32];

    int t = threadIdx.x;
    int p = t & 31, gi = t >> 5;

    const f16* base = g_conv + (size_t)b*DIM*HWc + pixbase;
    #pragma unroll
    for (int cc = 0; cc < 32; cc++) {
        int c = gi*32 + cc;
        s[c][p] = __half2float(base[(size_t)c*HWc + p]);
    }
    __syncthreads();

    float sum = 0.f, sq = 0.f;
    #pragma unroll
    for (int cc = 0; cc < 32; cc++) {
        float v = s[gi*32+cc][p];
        sum += v; sq = fmaf(v, v, sq);
    }
    psum[gi][p] = sum; psq[gi][p] = sq;
    __syncthreads();

    if (gi == 0) {
        float S = 0.f, Q = 0.f;
        #pragma unroll
        for (int k = 0; k < 8; k++) { S += psum[k][p]; Q += psq[k][p]; }
        float mu  = S * (1.f/DIM);
        float var = Q * (1.f/DIM) - mu*mu;
        mu_s[p] = mu;
        rs_s[p] = rsqrtf(var + 1e-6f);
    }
    __syncthreads();

    size_t tokbase = (size_t)b*HWc + pixbase;
    for (int i = t; i < 32*128; i += 256) {
        int pp = i >> 7, c2 = (i & 127) * 2;
        float mu = mu_s[pp], rs = rs_s[pp];
        float v0 = (s[c2  ][pp] - mu) * rs * gamma[c2  ] + beta[c2  ];
        float v1 = (s[c2+1][pp] - mu) * rs * gamma[c2+1] + beta[c2+1];
        *(uint32_t*)(g_a + (tokbase + pp)*DIM + c2) =
            pack2(__float2half_rn(v0), __float2half_rn(v1));
    }
}

// ------- 2b) transpose weights to fp16: w1[K,N]->w1t[N,K], w2 likewise -------
__global__ __launch_bounds__(256) void prep_w_kernel(
    const float* __restrict__ w1, const float* __restrict__ w2)
{
    int idx = blockIdx.x * 256 + threadIdx.x;
    if (idx < HID*DIM) {                       // w1t [n=1024][k=256]
        int n = idx >> 8, k = idx & 255;
        g_w1t[idx] = __float2half_rn(w1[(size_t)k*HID + n]);
    } else {                                   // w2t [n=256][k=1024]
        int j = idx - HID*DIM;
        int n = j >> 10, k = j & 1023;
        g_w2t[j] = __float2half_rn(w2[(size_t)k*DIM + n]);
    }
}

// ---------------- 3/4) HMMA fp16 GEMM (R10 exact, ~HW ceiling) ---------------
#define STAGE  32768
#define GSMEM  (3*STAGE)     // 98304

#define LDSMA(dst, base) do {            \
    LDSM4((dst)[0], (base));             \
    LDSM4((dst)[1], (base) + 2048);      \
    LDSM4((dst)[2], (base) + 4096);      \
    LDSM4((dst)[3], (base) + 6144); } while (0)
#define LDSMB(dst, base) do {            \
    uint32_t _r[4];                      \
    LDSM4(_r, (base));                   \
    (dst)[0][0]=_r[0]; (dst)[0][1]=_r[1]; (dst)[1][0]=_r[2]; (dst)[1][1]=_r[3]; \
    LDSM4(_r, (base) + 2048);            \
    (dst)[2][0]=_r[0]; (dst)[2][1]=_r[1]; (dst)[3][0]=_r[2]; (dst)[3][1]=_r[3]; } while (0)

template<int KTOT, int MODE>
__global__ __launch_bounds__(256, 2) void hgemm_kernel(
    const f16* __restrict__ A, const f16* __restrict__ Bw,
    const float* __restrict__ bias,
    f16* __restrict__ Oh, float* __restrict__ Of)
{
    extern __shared__ char smem[];
    __shared__ float sbias[128];

    const int tid  = threadIdx.x;
    const int wid  = tid >> 5, lane = tid & 31;
    const int warpM = wid >> 2, warpN = wid & 3;        // 2 x 4
    const int n0 = blockIdx.x * 128;
    const size_t m0 = (size_t)blockIdx.y * 128;

    if (tid < 128) sbias[tid] = bias[n0 + tid];

    const uint32_t sb = smem_u32(smem);

    const f16* Abase = A + m0 * KTOT;
    const f16* Bbase = Bw + (size_t)n0 * KTOT;
    const uint32_t soff0 = sw128((uint32_t)((tid >> 3)*128 + (tid & 7)*16));
    const uint32_t goff0 = (uint32_t)(tid >> 3) * (uint32_t)KTOT + (tid & 7)*8;

    auto load_stage = [&](int c, int s) {
        const uint32_t st = sb + s * STAGE + soff0;
        const f16* ga = Abase + goff0 + (uint32_t)c * 64;
        const f16* gb = Bbase + goff0 + (uint32_t)c * 64;
        #pragma unroll
        for (int it = 0; it < 4; it++) {
            CP16(st + it*4096,         ga + it*32*KTOT);
            CP16(st + 16384 + it*4096, gb + it*32*KTOT);
        }
    };

    const int j  = lane >> 3, lr = lane & 7;
    const uint32_t mask = (uint32_t)lr << 4;
    const uint32_t aoff0 = (uint32_t)(warpM*64 + ((j & 1) << 3) + lr)*128
                         + (((uint32_t)(j >> 1) << 4) ^ mask);
    const uint32_t boff0 = 16384
                         + (uint32_t)(warpN*32 + ((j >> 1) << 3) + lr)*128
                         + (((uint32_t)(j & 1) << 4) ^ mask);

    float acc[4][4][4] = {};
    uint32_t ah[2][4][4], bh[2][4][2];

    const int NC = KTOT / 64;
    load_stage(0, 0); CP_COMMIT();
    if (NC > 1) { load_stage(1, 1); CP_COMMIT(); }

    int s_use = 0, s_load = 2;
    #pragma unroll 1
    for (int c = 0; c < NC; c++) {
        if (c + 1 < NC) { CP_WAIT(1); } else { CP_WAIT(0); }
        __syncthreads();

        const uint32_t st = sb + s_use * STAGE;
        if (++s_use == 3) s_use = 0;
        const uint32_t a0 = st + aoff0, b0 = st + boff0;

        LDSMB(bh[0], b0);
        LDSMA(ah[0], a0);
        if (c + 2 < NC) {
            load_stage(c + 2, s_load); CP_COMMIT();
            if (++s_load == 3) s_load = 0;
        }

        #pragma unroll
        for (int ks = 0; ks < 4; ks++) {
            const int cur = ks & 1, nxt = cur ^ 1;
            if (ks < 3) {
                const uint32_t kx = 32u * (ks + 1);
                LDSMB(bh[nxt], b0 ^ kx);
                LDSMA(ah[nxt], a0 ^ kx);
            }
            #pragma unroll
            for (int mt = 0; mt < 4; mt++)
                #pragma unroll
                for (int nt = 0; nt < 4; nt++)
                    MMA16816(acc[mt][nt], ah[cur][mt],
                             bh[cur][nt][0], bh[cur][nt][1]);
        }
    }

    const int mlane = lane >> 2;
    const int nlane = (lane & 3) * 2;

    if (MODE == 1) {
        #pragma unroll
        for (int mt = 0; mt < 4; mt++) {
            const size_t mA = m0 + warpM*64 + mt*16 + mlane;
            #pragma unroll
            for (int nt = 0; nt < 4; nt++) {
                const int nc = warpN*32 + nt*8 + nlane;
                const float b0 = sbias[nc], b1 = sbias[nc + 1];
                #pragma unroll
                for (int half = 0; half < 2; half++) {
                    float v0 = gelu_fast(acc[mt][nt][half*2]     + b0);
                    float v1 = gelu_fast(acc[mt][nt][half*2 + 1] + b1);
                    size_t o = (mA + half*8) * (size_t)HID + n0 + nc;
                    *(uint32_t*)(Oh + o) = pack2(__float2half_rn(v0),
                                                 __float2half_rn(v1));
                }
            }
        }
    } else {
        __syncthreads();
        float* sf = (float*)smem;          // [128 n][132 m]
        #pragma unroll
        for (int mt = 0; mt < 4; mt++) {
            const int mA = warpM*64 + mt*16 + mlane;
            #pragma unroll
            for (int nt = 0; nt < 4; nt++) {
                const int nc = warpN*32 + nt*8 + nlane;
                sf[(nc    )*132 + mA    ] = acc[mt][nt][0];
                sf[(nc + 1)*132 + mA    ] = acc[mt][nt][1];
                sf[(nc    )*132 + mA + 8] = acc[mt][nt][2];
                sf[(nc + 1)*132 + mA + 8] = acc[mt][nt][3];
            }
        }
        __syncthreads();
        #pragma unroll 4
        for (int i = tid; i < 128*128; i += 256) {
            const int n = i >> 7, mm = i & 127;
            const int tok = (int)m0 + mm;
            const int b = tok / HWc, pix = tok % HWc;
            Of[((size_t)b*DIM + n0 + n)*HWc + pix] = sf[n*132 + mm] + sbias[n];
        }
    }
}

// ---------------- launch -----------------------------------------------------
extern "C" void kernel_launch(void* const* d_in, const int* in_sizes, int n_in,
                              void* d_out, int out_size)
{
    const float* x      = (const float*)d_in[0];
    const float* conv_w = (const float*)d_in[1];
    const float* conv_b = (const float*)d_in[2];
    const float* ln_g   = (const float*)d_in[3];
    const float* ln_b   = (const float*)d_in[4];
    const float* w1     = (const float*)d_in[5];
    const float* b1     = (const float*)d_in[6];
    const float* w2     = (const float*)d_in[7];
    const float* b2     = (const float*)d_in[8];
    float* out = (float*)d_out;

    f16 *p_a, *p_h, *p_w1t, *p_w2t;
    cudaGetSymbolAddress((void**)&p_a,   g_a);
    cudaGetSymbolAddress((void**)&p_h,   g_h);
    cudaGetSymbolAddress((void**)&p_w1t, g_w1t);
    cudaGetSymbolAddress((void**)&p_w2t, g_w2t);

    cudaFuncSetAttribute((const void*)hgemm_kernel<DIM, 1>,
                         cudaFuncAttributeMaxDynamicSharedMemorySize, GSMEM);
    cudaFuncSetAttribute((const void*)hgemm_kernel<HID, 2>,
                         cudaFuncAttributeMaxDynamicSharedMemorySize, GSMEM);

    dwconv_kernel<<<(Bc*DIM)/2, 224>>>(x, conv_w, conv_b);
    ln_kernel<<<TOK/32, 256>>>(ln_g, ln_b);
    prep_w_kernel<<<(2*HID*DIM)/256, 256>>>(w1, w2);

    // GEMM1: [TOK,256] x w1t -> GELU -> h (fp16)
    hgemm_kernel<DIM, 1><<<dim3(HID/128, TOK/128), 256, GSMEM>>>(
        p_a, p_w1t, b1, p_h, nullptr);
    // GEMM2: [TOK,1024] x w2t -> +b2 -> fp32 NCHW out
    hgemm_kernel<HID, 2><<<dim3(DIM/128, TOK/128), 256, GSMEM>>>(
        p_h, p_w2t, b2, nullptr, out);
}

// round 13
// speedup vs baseline: 1.0608x; 1.0383x over previous
#include <cuda_runtime.h>
#include <cuda_fp16.h>
#include <math.h>
#include <stdint.h>

#define Bc   32
#define DIM  256
#define Hc   56
#define Wc   56
#define HWc  (Hc*Wc)          // 3136
#define TOK  (Bc*HWc)         // 100352
#define HID  1024

typedef __half f16;

// ---------------- scratch (device globals; no runtime allocation) ------------
__device__ __align__(256) f16 g_conv[(size_t)Bc*DIM*HWc];    // conv out, NCHW f16
__device__ __align__(256) f16 g_a  [(size_t)TOK*DIM];        // LN out (fp16)
__device__ __align__(256) f16 g_h  [(size_t)TOK*HID];        // hidden (fp16)
__device__ __align__(256) f16 g_w1t[(size_t)HID*DIM];        // w1^T [N=1024][K=256]
__device__ __align__(256) f16 g_w2t[(size_t)DIM*HID];        // w2^T [N=256][K=1024]

// ---------------- asm primitives (base sm_103, no 'a' features) --------------
__device__ __forceinline__ uint32_t smem_u32(const void* p) {
    uint32_t a;
    asm("{ .reg .u64 t; cvta.to.shared.u64 t, %1; cvt.u32.u64 %0, t; }"
        : "=r"(a) : "l"(p));
    return a;
}
#define CP16(dst, src) \
    asm volatile("cp.async.cg.shared.global [%0], [%1], 16;" \
                 :: "r"(dst), "l"(src) : "memory")
#define CP_COMMIT() asm volatile("cp.async.commit_group;" ::: "memory")
#define CP_WAIT(n)  asm volatile("cp.async.wait_group %0;" :: "n"(n) : "memory")
#define LDSM4(r, addr) \
    asm volatile("ldmatrix.sync.aligned.m8n8.x4.shared.b16 {%0,%1,%2,%3}, [%4];" \
                 : "=r"((r)[0]), "=r"((r)[1]), "=r"((r)[2]), "=r"((r)[3]) \
                 : "r"(addr))
#define MMA16816(d, a, b0v, b1v) \
    asm volatile("mma.sync.aligned.m16n8k16.row.col.f32.f16.f16.f32 " \
                 "{%0,%1,%2,%3}, {%4,%5,%6,%7}, {%8,%9}, {%0,%1,%2,%3};" \
                 : "+f"((d)[0]), "+f"((d)[1]), "+f"((d)[2]), "+f"((d)[3]) \
                 : "r"((a)[0]), "r"((a)[1]), "r"((a)[2]), "r"((a)[3]), \
                   "r"(b0v), "r"(b1v))

__device__ __forceinline__ uint32_t sw128(uint32_t off) {
    return off ^ ((off >> 3) & 0x70);
}
__device__ __forceinline__ uint32_t pack2(f16 a, f16 b) {
    return (uint32_t)*(uint16_t*)&a | ((uint32_t)*(uint16_t*)&b << 16);
}

// Fast exact-GELU: Abramowitz-Stegun 7.1.26 erf (|abs err| <= 1.5e-7).
__device__ __forceinline__ float gelu_fast(float x) {
    const float t = fabsf(x) * 0.70710678118654752f;
    const float u = __fdividef(1.f, fmaf(0.3275911f, t, 1.f));
    float p = fmaf(1.061405429f, u, -1.453152027f);
    p = fmaf(p, u, 1.421413741f);
    p = fmaf(p, u, -0.284496736f);
    p = fmaf(p, u, 0.254829592f);
    p = p * u;
    const float e  = __expf(-t * t);
    const float er = copysignf(fmaf(-p, e, 1.f), x);
    return 0.5f * x * (1.f + er);
}

// ------- 1) depthwise 7x7 conv + bias: one block per (b,c) plane (R10 exact) -
__global__ __launch_bounds__(256) void dwconv_kernel(
    const float* __restrict__ x, const float* __restrict__ cw,
    const float* __restrict__ cb)
{
    const int bc = blockIdx.x;            // b*DIM + c
    const int c  = bc & (DIM-1);

    __shared__ float sx[62][64];          // rows -3..58, cols -3..60 (pad 64)
    __shared__ float sw[49];

    const float* xp = x + (size_t)bc*HWc;
    const int t = threadIdx.x;
    if (t < 49) sw[t] = cw[c*49 + t];

    for (int i = t; i < 62*64; i += 256) {
        const int r = i >> 6, col = i & 63;
        const int gr = r - 3, gc = col - 3;
        float v = 0.f;
        if (gr >= 0 && gr < Hc && gc >= 0 && gc < Wc)
            v = xp[gr*Wc + gc];
        sx[r][col] = v;
    }
    __syncthreads();

    const float bias = cb[c];
    f16* op = g_conv + (size_t)bc*HWc;
    const int col = t & 63, r0 = t >> 6;  // 4 rows x 64 cols per iteration
    if (col < Wc) {
        #pragma unroll
        for (int rr = r0; rr < Hc; rr += 4) {
            float acc = bias;
            #pragma unroll
            for (int ki = 0; ki < 7; ki++)
                #pragma unroll
                for (int kj = 0; kj < 7; kj++)
                    acc = fmaf(sx[rr+ki][col+kj], sw[ki*7+kj], acc);
            op[rr*Wc + col] = __float2half_rn(acc);
        }
    }
}

// ------- 2) LayerNorm over channels + NCHW->NHWC, emit fp16 (R10 exact) ------
__global__ __launch_bounds__(256) void ln_kernel(
    const float* __restrict__ gamma, const float* __restrict__ beta)
{
    int tile = blockIdx.x;
    int b    = tile / (HWc/32);
    int pixbase = (tile % (HWc/32)) * 32;

    __shared__ float s[DIM][33];
    __shared__ float psum[8][32], psq[8][32];
    __shared__ float mu_s[32], rs_s[32];

    int t = threadIdx.x;
    int p = t & 31, gi = t >> 5;

    const f16* base = g_conv + (size_t)b*DIM*HWc + pixbase;
    #pragma unroll
    for (int cc = 0; cc < 32; cc++) {
        int c = gi*32 + cc;
        s[c][p] = __half2float(base[(size_t)c*HWc + p]);
    }
    __syncthreads();

    float sum = 0.f, sq = 0.f;
    #pragma unroll
    for (int cc = 0; cc < 32; cc++) {
        float v = s[gi*32+cc][p];
        sum += v; sq = fmaf(v, v, sq);
    }
    psum[gi][p] = sum; psq[gi][p] = sq;
    __syncthreads();

    if (gi == 0) {
        float S = 0.f, Q = 0.f;
        #pragma unroll
        for (int k = 0; k < 8; k++) { S += psum[k][p]; Q += psq[k][p]; }
        float mu  = S * (1.f/DIM);
        float var = Q * (1.f/DIM) - mu*mu;
        mu_s[p] = mu;
        rs_s[p] = rsqrtf(var + 1e-6f);
    }
    __syncthreads();

    size_t tokbase = (size_t)b*HWc + pixbase;
    for (int i = t; i < 32*128; i += 256) {
        int pp = i >> 7, c2 = (i & 127) * 2;
        float mu = mu_s[pp], rs = rs_s[pp];
        float v0 = (s[c2  ][pp] - mu) * rs * gamma[c2  ] + beta[c2  ];
        float v1 = (s[c2+1][pp] - mu) * rs * gamma[c2+1] + beta[c2+1];
        *(uint32_t*)(g_a + (tokbase + pp)*DIM + c2) =
            pack2(__float2half_rn(v0), __float2half_rn(v1));
    }
}

// ------- 2b) transpose weights to fp16: w1[K,N]->w1t[N,K], w2 likewise -------
__global__ __launch_bounds__(256) void prep_w_kernel(
    const float* __restrict__ w1, const float* __restrict__ w2)
{
    int idx = blockIdx.x * 256 + threadIdx.x;
    if (idx < HID*DIM) {                       // w1t [n=1024][k=256]
        int n = idx >> 8, k = idx & 255;
        g_w1t[idx] = __float2half_rn(w1[(size_t)k*HID + n]);
    } else {                                   // w2t [n=256][k=1024]
        int j = idx - HID*DIM;
        int n = j >> 10, k = j & 1023;
        g_w2t[j] = __float2half_rn(w2[(size_t)k*DIM + n]);
    }
}

// ---------------- 3/4) HMMA fp16 GEMM, CTM-templated (R10 structure) ---------
// CTA tile CTM x 128, BK=64, 256 threads, 2 CTAs/SM, 3-stage cp.async.
// CTM=128 (GEMM1, 21 waves) / CTM=64 (GEMM2: 3136 CTAs = 10.6 waves,
// kills the 13% wave-quantization tail of the 1568-CTA version).
// MODE 1: out = fp16(gelu_fast(acc+bias)) -> Oh [tok][HID]
// MODE 2: out = acc+bias -> fp32 NCHW (smem-transposed, coalesced)

template<int KTOT, int MODE, int CTM>
__global__ __launch_bounds__(256, 2) void hgemm_kernel(
    const f16* __restrict__ A, const f16* __restrict__ Bw,
    const float* __restrict__ bias,
    f16* __restrict__ Oh, float* __restrict__ Of)
{
    constexpr int MT     = CTM / 32;          // m-tiles per warp
    constexpr int ABYTES = CTM * 128;         // A tile bytes per stage
    constexpr int STAGEB = ABYTES + 16384;    // + B tile (128 x 64 f16)

    extern __shared__ char smem[];
    __shared__ float sbias[128];

    const int tid  = threadIdx.x;
    const int wid  = tid >> 5, lane = tid & 31;
    const int warpM = wid >> 2, warpN = wid & 3;        // 2 x 4
    const int n0 = blockIdx.x * 128;
    const size_t m0 = (size_t)blockIdx.y * CTM;

    if (tid < 128) sbias[tid] = bias[n0 + tid];

    const uint32_t sb = smem_u32(smem);

    const f16* Abase = A + m0 * KTOT;
    const f16* Bbase = Bw + (size_t)n0 * KTOT;
    const uint32_t soff0 = sw128((uint32_t)((tid >> 3)*128 + (tid & 7)*16));
    const uint32_t goff0 = (uint32_t)(tid >> 3) * (uint32_t)KTOT + (tid & 7)*8;

    auto load_stage = [&](int c, int s) {
        const uint32_t st = sb + s * STAGEB + soff0;
        const f16* ga = Abase + goff0 + (uint32_t)c * 64;
        const f16* gb = Bbase + goff0 + (uint32_t)c * 64;
        #pragma unroll
        for (int it = 0; it < MT; it++)                 // A: CTM rows
            CP16(st + it*4096, ga + it*32*KTOT);
        #pragma unroll
        for (int it = 0; it < 4; it++)                  // B: 128 rows
            CP16(st + ABYTES + it*4096, gb + it*32*KTOT);
    };

    const int j  = lane >> 3, lr = lane & 7;
    const uint32_t mask = (uint32_t)lr << 4;
    const uint32_t aoff0 = (uint32_t)(warpM*(CTM/2) + ((j & 1) << 3) + lr)*128
                         + (((uint32_t)(j >> 1) << 4) ^ mask);
    const uint32_t boff0 = ABYTES
                         + (uint32_t)(warpN*32 + ((j >> 1) << 3) + lr)*128
                         + (((uint32_t)(j & 1) << 4) ^ mask);

    float acc[MT][4][4] = {};
    uint32_t ah[2][MT][4], bh[2][4][2];

    const int NC = KTOT / 64;
    load_stage(0, 0); CP_COMMIT();
    if (NC > 1) { load_stage(1, 1); CP_COMMIT(); }

    int s_use = 0, s_load = 2;
    #pragma unroll 1
    for (int c = 0; c < NC; c++) {
        if (c + 1 < NC) { CP_WAIT(1); } else { CP_WAIT(0); }
        __syncthreads();

        const uint32_t st = sb + s_use * STAGEB;
        if (++s_use == 3) s_use = 0;
        const uint32_t a0 = st + aoff0, b0 = st + boff0;

        // prefetch ks=0 fragments
        {
            uint32_t r[4];
            LDSM4(r, b0);
            bh[0][0][0]=r[0]; bh[0][0][1]=r[1]; bh[0][1][0]=r[2]; bh[0][1][1]=r[3];
            LDSM4(r, b0 + 2048);
            bh[0][2][0]=r[0]; bh[0][2][1]=r[1]; bh[0][3][0]=r[2]; bh[0][3][1]=r[3];
            #pragma unroll
            for (int mt = 0; mt < MT; mt++) LDSM4(ah[0][mt], a0 + mt*2048);
        }
        if (c + 2 < NC) {
            load_stage(c + 2, s_load); CP_COMMIT();
            if (++s_load == 3) s_load = 0;
        }

        #pragma unroll
        for (int ks = 0; ks < 4; ks++) {
            const int cur = ks & 1, nxt = cur ^ 1;
            if (ks < 3) {                          // LDSM(ks+1) overlaps MMA(ks)
                const uint32_t kx = 32u * (ks + 1);
                uint32_t r[4];
                LDSM4(r, (b0 ^ kx));
                bh[nxt][0][0]=r[0]; bh[nxt][0][1]=r[1];
                bh[nxt][1][0]=r[2]; bh[nxt][1][1]=r[3];
                LDSM4(r, (b0 ^ kx) + 2048);
                bh[nxt][2][0]=r[0]; bh[nxt][2][1]=r[1];
                bh[nxt][3][0]=r[2]; bh[nxt][3][1]=r[3];
                #pragma unroll
                for (int mt = 0; mt < MT; mt++)
                    LDSM4(ah[nxt][mt], (a0 ^ kx) + mt*2048);
            }
            #pragma unroll
            for (int mt = 0; mt < MT; mt++)
                #pragma unroll
                for (int nt = 0; nt < 4; nt++)
                    MMA16816(acc[mt][nt], ah[cur][mt],
                             bh[cur][nt][0], bh[cur][nt][1]);
        }
    }

    const int mlane = lane >> 2;
    const int nlane = (lane & 3) * 2;

    if (MODE == 1) {
        #pragma unroll
        for (int mt = 0; mt < MT; mt++) {
            const size_t mA = m0 + warpM*(CTM/2) + mt*16 + mlane;
            #pragma unroll
            for (int nt = 0; nt < 4; nt++) {
                const int nc = warpN*32 + nt*8 + nlane;
                const float b0 = sbias[nc], b1 = sbias[nc + 1];
                #pragma unroll
                for (int half = 0; half < 2; half++) {
                    float v0 = gelu_fast(acc[mt][nt][half*2]     + b0);
                    float v1 = gelu_fast(acc[mt][nt][half*2 + 1] + b1);
                    size_t o = (mA + half*8) * (size_t)HID + n0 + nc;
                    *(uint32_t*)(Oh + o) = pack2(__float2half_rn(v0),
                                                 __float2half_rn(v1));
                }
            }
        }
    } else {
        __syncthreads();
        float* sf = (float*)smem;          // [128 n][CTM+4 m]
        #pragma unroll
        for (int mt = 0; mt < MT; mt++) {
            const int mA = warpM*(CTM/2) + mt*16 + mlane;
            #pragma unroll
            for (int nt = 0; nt < 4; nt++) {
                const int nc = warpN*32 + nt*8 + nlane;
                sf[(nc    )*(CTM+4) + mA    ] = acc[mt][nt][0];
                sf[(nc + 1)*(CTM+4) + mA    ] = acc[mt][nt][1];
                sf[(nc    )*(CTM+4) + mA + 8] = acc[mt][nt][2];
                sf[(nc + 1)*(CTM+4) + mA + 8] = acc[mt][nt][3];
            }
        }
        __syncthreads();
        #pragma unroll 4
        for (int i = tid; i < 128*CTM; i += 256) {
            const int n = i / CTM, mm = i % CTM;
            const int tok = (int)m0 + mm;
            const int b = tok / HWc, pix = tok % HWc;
            Of[((size_t)b*DIM + n0 + n)*HWc + pix] = sf[n*(CTM+4) + mm] + sbias[n];
        }
    }
}

// ---------------- launch -----------------------------------------------------
extern "C" void kernel_launch(void* const* d_in, const int* in_sizes, int n_in,
                              void* d_out, int out_size)
{
    const float* x      = (const float*)d_in[0];
    const float* conv_w = (const float*)d_in[1];
    const float* conv_b = (const float*)d_in[2];
    const float* ln_g   = (const float*)d_in[3];
    const float* ln_b   = (const float*)d_in[4];
    const float* w1     = (const float*)d_in[5];
    const float* b1     = (const float*)d_in[6];
    const float* w2     = (const float*)d_in[7];
    const float* b2     = (const float*)d_in[8];
    float* out = (float*)d_out;

    f16 *p_a, *p_h, *p_w1t, *p_w2t;
    cudaGetSymbolAddress((void**)&p_a,   g_a);
    cudaGetSymbolAddress((void**)&p_h,   g_h);
    cudaGetSymbolAddress((void**)&p_w1t, g_w1t);
    cudaGetSymbolAddress((void**)&p_w2t, g_w2t);

    constexpr int SMEM1 = 3 * (128*128 + 16384);   // 98304
    constexpr int SMEM2 = 3 * ( 64*128 + 16384);   // 73728
    cudaFuncSetAttribute((const void*)hgemm_kernel<DIM, 1, 128>,
                         cudaFuncAttributeMaxDynamicSharedMemorySize, SMEM1);
    cudaFuncSetAttribute((const void*)hgemm_kernel<HID, 2, 64>,
                         cudaFuncAttributeMaxDynamicSharedMemorySize, SMEM2);

    dwconv_kernel<<<Bc*DIM, 256>>>(x, conv_w, conv_b);
    ln_kernel<<<TOK/32, 256>>>(ln_g, ln_b);
    prep_w_kernel<<<(2*HID*DIM)/256, 256>>>(w1, w2);

    // GEMM1: [TOK,256] x w1t -> GELU -> h (fp16); 128x128 tiles, 21.2 waves
    hgemm_kernel<DIM, 1, 128><<<dim3(HID/128, TOK/128), 256, SMEM1>>>(
        p_a, p_w1t, b1, p_h, nullptr);
    // GEMM2: [TOK,1024] x w2t -> +b2 -> fp32 NCHW; 64x128 tiles, 10.6 waves
    hgemm_kernel<HID, 2, 64><<<dim3(DIM/128, TOK/64), 256, SMEM2>>>(
        p_h, p_w2t, b2, nullptr, out);
}

// round 14
// speedup vs baseline: 1.1080x; 1.0445x over previous
#include <cuda_runtime.h>
#include <cuda_fp16.h>
#include <math.h>
#include <stdint.h>

#define Bc   32
#define DIM  256
#define Hc   56
#define Wc   56
#define HWc  (Hc*Wc)          // 3136
#define TOK  (Bc*HWc)         // 100352
#define HID  1024

typedef __half f16;

// ---------------- scratch (device globals; no runtime allocation) ------------
__device__ __align__(256) f16 g_conv[(size_t)Bc*DIM*HWc];    // conv out, NCHW f16
__device__ __align__(256) f16 g_a  [(size_t)TOK*DIM];        // LN out (fp16)
__device__ __align__(256) f16 g_h  [(size_t)TOK*HID];        // hidden (fp16)
__device__ __align__(256) f16 g_w1t[(size_t)HID*DIM];        // w1^T [N=1024][K=256]
__device__ __align__(256) f16 g_w2t[(size_t)DIM*HID];        // w2^T [N=256][K=1024]

// ---------------- asm primitives (base sm_103, no 'a' features) --------------
__device__ __forceinline__ uint32_t smem_u32(const void* p) {
    uint32_t a;
    asm("{ .reg .u64 t; cvta.to.shared.u64 t, %1; cvt.u32.u64 %0, t; }"
        : "=r"(a) : "l"(p));
    return a;
}
#define CP16(dst, src) \
    asm volatile("cp.async.cg.shared.global [%0], [%1], 16;" \
                 :: "r"(dst), "l"(src) : "memory")
#define CP_COMMIT() asm volatile("cp.async.commit_group;" ::: "memory")
#define CP_WAIT(n)  asm volatile("cp.async.wait_group %0;" :: "n"(n) : "memory")
#define LDSM4(r, addr) \
    asm volatile("ldmatrix.sync.aligned.m8n8.x4.shared.b16 {%0,%1,%2,%3}, [%4];" \
                 : "=r"((r)[0]), "=r"((r)[1]), "=r"((r)[2]), "=r"((r)[3]) \
                 : "r"(addr))
#define MMA16816(d, a, b0v, b1v) \
    asm volatile("mma.sync.aligned.m16n8k16.row.col.f32.f16.f16.f32 " \
                 "{%0,%1,%2,%3}, {%4,%5,%6,%7}, {%8,%9}, {%0,%1,%2,%3};" \
                 : "+f"((d)[0]), "+f"((d)[1]), "+f"((d)[2]), "+f"((d)[3]) \
                 : "r"((a)[0]), "r"((a)[1]), "r"((a)[2]), "r"((a)[3]), \
                   "r"(b0v), "r"(b1v))

__device__ __forceinline__ uint32_t sw128(uint32_t off) {
    return off ^ ((off >> 3) & 0x70);
}
// single-instruction packed conversion (cvt.rn.f16x2.f32)
__device__ __forceinline__ uint32_t pack2f(float a, float b) {
    const __half2 h = __float22half2_rn(make_float2(a, b));
    return *(const uint32_t*)&h;
}

// Fast exact-GELU: Abramowitz-Stegun 7.1.26 erf (|abs err| <= 1.5e-7).
__device__ __forceinline__ float gelu_fast(float x) {
    const float t = fabsf(x) * 0.70710678118654752f;
    const float u = __fdividef(1.f, fmaf(0.3275911f, t, 1.f));
    float p = fmaf(1.061405429f, u, -1.453152027f);
    p = fmaf(p, u, 1.421413741f);
    p = fmaf(p, u, -0.284496736f);
    p = fmaf(p, u, 0.254829592f);
    p = p * u;
    const float e  = __expf(-t * t);
    const float er = copysignf(fmaf(-p, e, 1.f), x);
    return 0.5f * x * (1.f + er);
}

// ------- 1) depthwise 7x7 conv + bias (R10 exact) + fused weight-prep --------
// Blocks [0, Bc*DIM): conv, one block per (b,c) plane.
// Blocks [Bc*DIM, Bc*DIM + 2048): transpose w1/w2 to fp16 (prep_w folded in,
// saving one kernel launch + tail wave).
__global__ __launch_bounds__(256) void dwconv_kernel(
    const float* __restrict__ x, const float* __restrict__ cw,
    const float* __restrict__ cb,
    const float* __restrict__ w1, const float* __restrict__ w2)
{
    const int t = threadIdx.x;

    if (blockIdx.x >= Bc*DIM) {               // ---- weight-prep path ----
        const int idx = (blockIdx.x - Bc*DIM) * 256 + t;
        if (idx < HID*DIM) {                  // w1t [n=1024][k=256]
            const int n = idx >> 8, k = idx & 255;
            g_w1t[idx] = __float2half_rn(w1[(size_t)k*HID + n]);
        } else {                              // w2t [n=256][k=1024]
            const int j = idx - HID*DIM;
            const int n = j >> 10, k = j & 1023;
            g_w2t[j] = __float2half_rn(w2[(size_t)k*DIM + n]);
        }
        return;
    }

    const int bc = blockIdx.x;                // b*DIM + c
    const int c  = bc & (DIM-1);

    __shared__ float sx[62][64];              // rows -3..58, cols -3..60
    __shared__ float sw[49];

    const float* xp = x + (size_t)bc*HWc;
    if (t < 49) sw[t] = cw[c*49 + t];

    for (int i = t; i < 62*64; i += 256) {
        const int r = i >> 6, col = i & 63;
        const int gr = r - 3, gc = col - 3;
        float v = 0.f;
        if (gr >= 0 && gr < Hc && gc >= 0 && gc < Wc)
            v = xp[gr*Wc + gc];
        sx[r][col] = v;
    }
    __syncthreads();

    const float bias = cb[c];
    f16* op = g_conv + (size_t)bc*HWc;
    const int col = t & 63, r0 = t >> 6;      // 4 rows x 64 cols per iteration
    if (col < Wc) {
        #pragma unroll
        for (int rr = r0; rr < Hc; rr += 4) {
            float acc = bias;
            #pragma unroll
            for (int ki = 0; ki < 7; ki++)
                #pragma unroll
                for (int kj = 0; kj < 7; kj++)
                    acc = fmaf(sx[rr+ki][col+kj], sw[ki*7+kj], acc);
            op[rr*Wc + col] = __float2half_rn(acc);
        }
    }
}

// ------- 2) LayerNorm over channels + NCHW->NHWC, emit fp16 (R10 exact) ------
__global__ __launch_bounds__(256) void ln_kernel(
    const float* __restrict__ gamma, const float* __restrict__ beta)
{
    int tile = blockIdx.x;
    int b    = tile / (HWc/32);
    int pixbase = (tile % (HWc/32)) * 32;

    __shared__ float s[DIM][33];
    __shared__ float psum[8][32], psq[8][32];
    __shared__ float mu_s[32], rs_s[32];

    int t = threadIdx.x;
    int p = t & 31, gi = t >> 5;

    const f16* base = g_conv + (size_t)b*DIM*HWc + pixbase;
    #pragma unroll
    for (int cc = 0; cc < 32; cc++) {
        int c = gi*32 + cc;
        s[c][p] = __half2float(base[(size_t)c*HWc + p]);
    }
    __syncthreads();

    float sum = 0.f, sq = 0.f;
    #pragma unroll
    for (int cc = 0; cc < 32; cc++) {
        float v = s[gi*32+cc][p];
        sum += v; sq = fmaf(v, v, sq);
    }
    psum[gi][p] = sum; psq[gi][p] = sq;
    __syncthreads();

    if (gi == 0) {
        float S = 0.f, Q = 0.f;
        #pragma unroll
        for (int k = 0; k < 8; k++) { S += psum[k][p]; Q += psq[k][p]; }
        float mu  = S * (1.f/DIM);
        float var = Q * (1.f/DIM) - mu*mu;
        mu_s[p] = mu;
        rs_s[p] = rsqrtf(var + 1e-6f);
    }
    __syncthreads();

    size_t tokbase = (size_t)b*HWc + pixbase;
    for (int i = t; i < 32*128; i += 256) {
        int pp = i >> 7, c2 = (i & 127) * 2;
        float mu = mu_s[pp], rs = rs_s[pp];
        float v0 = (s[c2  ][pp] - mu) * rs * gamma[c2  ] + beta[c2  ];
        float v1 = (s[c2+1][pp] - mu) * rs * gamma[c2+1] + beta[c2+1];
        *(uint32_t*)(g_a + (tokbase + pp)*DIM + c2) = pack2f(v0, v1);
    }
}

// ---------------- 3/4) HMMA fp16 GEMM (R10 exact, ~HW ceiling) ---------------
#define STAGE  32768
#define GSMEM  (3*STAGE)     // 98304

#define LDSMA(dst, base) do {            \
    LDSM4((dst)[0], (base));             \
    LDSM4((dst)[1], (base) + 2048);      \
    LDSM4((dst)[2], (base) + 4096);      \
    LDSM4((dst)[3], (base) + 6144); } while (0)
#define LDSMB(dst, base) do {            \
    uint32_t _r[4];                      \
    LDSM4(_r, (base));                   \
    (dst)[0][0]=_r[0]; (dst)[0][1]=_r[1]; (dst)[1][0]=_r[2]; (dst)[1][1]=_r[3]; \
    LDSM4(_r, (base) + 2048);            \
    (dst)[2][0]=_r[0]; (dst)[2][1]=_r[1]; (dst)[3][0]=_r[2]; (dst)[3][1]=_r[3]; } while (0)

template<int KTOT, int MODE>
__global__ __launch_bounds__(256, 2) void hgemm_kernel(
    const f16* __restrict__ A, const f16* __restrict__ Bw,
    const float* __restrict__ bias,
    f16* __restrict__ Oh, float* __restrict__ Of)
{
    extern __shared__ char smem[];
    __shared__ float sbias[128];

    const int tid  = threadIdx.x;
    const int wid  = tid >> 5, lane = tid & 31;
    const int warpM = wid >> 2, warpN = wid & 3;        // 2 x 4
    const int n0 = blockIdx.x * 128;
    const size_t m0 = (size_t)blockIdx.y * 128;

    if (tid < 128) sbias[tid] = bias[n0 + tid];

    const uint32_t sb = smem_u32(smem);

    const f16* Abase = A + m0 * KTOT;
    const f16* Bbase = Bw + (size_t)n0 * KTOT;
    const uint32_t soff0 = sw128((uint32_t)((tid >> 3)*128 + (tid & 7)*16));
    const uint32_t goff0 = (uint32_t)(tid >> 3) * (uint32_t)KTOT + (tid & 7)*8;

    auto load_stage = [&](int c, int s) {
        const uint32_t st = sb + s * STAGE + soff0;
        const f16* ga = Abase + goff0 + (uint32_t)c * 64;
        const f16* gb = Bbase + goff0 + (uint32_t)c * 64;
        #pragma unroll
        for (int it = 0; it < 4; it++) {
            CP16(st + it*4096,         ga + it*32*KTOT);
            CP16(st + 16384 + it*4096, gb + it*32*KTOT);
        }
    };

    const int j  = lane >> 3, lr = lane & 7;
    const uint32_t mask = (uint32_t)lr << 4;
    const uint32_t aoff0 = (uint32_t)(warpM*64 + ((j & 1) << 3) + lr)*128
                         + (((uint32_t)(j >> 1) << 4) ^ mask);
    const uint32_t boff0 = 16384
                         + (uint32_t)(warpN*32 + ((j >> 1) << 3) + lr)*128
                         + (((uint32_t)(j & 1) << 4) ^ mask);

    float acc[4][4][4] = {};
    uint32_t ah[2][4][4], bh[2][4][2];

    const int NC = KTOT / 64;
    load_stage(0, 0); CP_COMMIT();
    if (NC > 1) { load_stage(1, 1); CP_COMMIT(); }

    int s_use = 0, s_load = 2;
    #pragma unroll 1
    for (int c = 0; c < NC; c++) {
        if (c + 1 < NC) { CP_WAIT(1); } else { CP_WAIT(0); }
        __syncthreads();

        const uint32_t st = sb + s_use * STAGE;
        if (++s_use == 3) s_use = 0;
        const uint32_t a0 = st + aoff0, b0 = st + boff0;

        LDSMB(bh[0], b0);
        LDSMA(ah[0], a0);
        if (c + 2 < NC) {
            load_stage(c + 2, s_load); CP_COMMIT();
            if (++s_load == 3) s_load = 0;
        }

        #pragma unroll
        for (int ks = 0; ks < 4; ks++) {
            const int cur = ks & 1, nxt = cur ^ 1;
            if (ks < 3) {
                const uint32_t kx = 32u * (ks + 1);
                LDSMB(bh[nxt], b0 ^ kx);
                LDSMA(ah[nxt], a0 ^ kx);
            }
            #pragma unroll
            for (int mt = 0; mt < 4; mt++)
                #pragma unroll
                for (int nt = 0; nt < 4; nt++)
                    MMA16816(acc[mt][nt], ah[cur][mt],
                             bh[cur][nt][0], bh[cur][nt][1]);
        }
    }

    const int mlane = lane >> 2;
    const int nlane = (lane & 3) * 2;

    if (MODE == 1) {
        #pragma unroll
        for (int mt = 0; mt < 4; mt++) {
            const size_t mA = m0 + warpM*64 + mt*16 + mlane;
            #pragma unroll
            for (int nt = 0; nt < 4; nt++) {
                const int nc = warpN*32 + nt*8 + nlane;
                const float b0 = sbias[nc], b1 = sbias[nc + 1];
                #pragma unroll
                for (int half = 0; half < 2; half++) {
                    float v0 = gelu_fast(acc[mt][nt][half*2]     + b0);
                    float v1 = gelu_fast(acc[mt][nt][half*2 + 1] + b1);
                    size_t o = (mA + half*8) * (size_t)HID + n0 + nc;
                    *(uint32_t*)(Oh + o) = pack2f(v0, v1);
                }
            }
        }
    } else {
        __syncthreads();
        float* sf = (float*)smem;          // [128 n][132 m]
        #pragma unroll
        for (int mt = 0; mt < 4; mt++) {
            const int mA = warpM*64 + mt*16 + mlane;
            #pragma unroll
            for (int nt = 0; nt < 4; nt++) {
                const int nc = warpN*32 + nt*8 + nlane;
                sf[(nc    )*132 + mA    ] = acc[mt][nt][0];
                sf[(nc + 1)*132 + mA    ] = acc[mt][nt][1];
                sf[(nc    )*132 + mA + 8] = acc[mt][nt][2];
                sf[(nc + 1)*132 + mA + 8] = acc[mt][nt][3];
            }
        }
        __syncthreads();
        #pragma unroll 4
        for (int i = tid; i < 128*128; i += 256) {
            const int n = i >> 7, mm = i & 127;
            const int tok = (int)m0 + mm;
            const int b = tok / HWc, pix = tok % HWc;
            Of[((size_t)b*DIM + n0 + n)*HWc + pix] = sf[n*132 + mm] + sbias[n];
        }
    }
}

// ---------------- launch -----------------------------------------------------
extern "C" void kernel_launch(void* const* d_in, const int* in_sizes, int n_in,
                              void* d_out, int out_size)
{
    const float* x      = (const float*)d_in[0];
    const float* conv_w = (const float*)d_in[1];
    const float* conv_b = (const float*)d_in[2];
    const float* ln_g   = (const float*)d_in[3];
    const float* ln_b   = (const float*)d_in[4];
    const float* w1     = (const float*)d_in[5];
    const float* b1     = (const float*)d_in[6];
    const float* w2     = (const float*)d_in[7];
    const float* b2     = (const float*)d_in[8];
    float* out = (float*)d_out;

    f16 *p_a, *p_h, *p_w1t, *p_w2t;
    cudaGetSymbolAddress((void**)&p_a,   g_a);
    cudaGetSymbolAddress((void**)&p_h,   g_h);
    cudaGetSymbolAddress((void**)&p_w1t, g_w1t);
    cudaGetSymbolAddress((void**)&p_w2t, g_w2t);

    cudaFuncSetAttribute((const void*)hgemm_kernel<DIM, 1>,
                         cudaFuncAttributeMaxDynamicSharedMemorySize, GSMEM);
    cudaFuncSetAttribute((const void*)hgemm_kernel<HID, 2>,
                         cudaFuncAttributeMaxDynamicSharedMemorySize, GSMEM);

    // conv (8192 blocks) + fused weight-prep (2048 blocks)
    dwconv_kernel<<<Bc*DIM + (2*HID*DIM)/256, 256>>>(x, conv_w, conv_b, w1, w2);
    ln_kernel<<<TOK/32, 256>>>(ln_g, ln_b);

    // GEMM1: [TOK,256] x w1t -> GELU -> h (fp16)
    hgemm_kernel<DIM, 1><<<dim3(HID/128, TOK/128), 256, GSMEM>>>(
        p_a, p_w1t, b1, p_h, nullptr);
    // GEMM2: [TOK,1024] x w2t -> +b2 -> fp32 NCHW out
    hgemm_kernel<HID, 2><<<dim3(DIM/128, TOK/128), 256, GSMEM>>>(
        p_h, p_w2t, b2, nullptr, out);
}

// round 15
// speedup vs baseline: 1.1929x; 1.0766x over previous
#include <cuda_runtime.h>
#include <cuda_fp16.h>
#include <math.h>
#include <stdint.h>

#define Bc   32
#define DIM  256
#define Hc   56
#define Wc   56
#define HWc  (Hc*Wc)          // 3136
#define TOK  (Bc*HWc)         // 100352
#define HID  1024

typedef __half f16;

// ---------------- scratch (device globals; no runtime allocation) ------------
__device__ __align__(256) f16 g_conv[(size_t)Bc*DIM*HWc];    // conv out, NCHW f16
__device__ __align__(256) f16 g_a  [(size_t)TOK*DIM];        // LN out (fp16)
__device__ __align__(256) f16 g_h  [(size_t)TOK*HID];        // hidden (fp16)
__device__ __align__(256) f16 g_w1t[(size_t)HID*DIM];        // w1^T [N=1024][K=256]
__device__ __align__(256) f16 g_w2t[(size_t)DIM*HID];        // w2^T [N=256][K=1024]

// ---------------- asm primitives (base sm_103, no 'a' features) --------------
__device__ __forceinline__ uint32_t smem_u32(const void* p) {
    uint32_t a;
    asm("{ .reg .u64 t; cvta.to.shared.u64 t, %1; cvt.u32.u64 %0, t; }"
        : "=r"(a) : "l"(p));
    return a;
}
#define CP16(dst, src) \
    asm volatile("cp.async.cg.shared.global [%0], [%1], 16;" \
                 :: "r"(dst), "l"(src) : "memory")
#define CP_COMMIT() asm volatile("cp.async.commit_group;" ::: "memory")
#define CP_WAIT(n)  asm volatile("cp.async.wait_group %0;" :: "n"(n) : "memory")
#define LDSM4(r, addr) \
    asm volatile("ldmatrix.sync.aligned.m8n8.x4.shared.b16 {%0,%1,%2,%3}, [%4];" \
                 : "=r"((r)[0]), "=r"((r)[1]), "=r"((r)[2]), "=r"((r)[3]) \
                 : "r"(addr))
#define MMA16816(d, a, b0v, b1v) \
    asm volatile("mma.sync.aligned.m16n8k16.row.col.f32.f16.f16.f32 " \
                 "{%0,%1,%2,%3}, {%4,%5,%6,%7}, {%8,%9}, {%0,%1,%2,%3};" \
                 : "+f"((d)[0]), "+f"((d)[1]), "+f"((d)[2]), "+f"((d)[3]) \
                 : "r"((a)[0]), "r"((a)[1]), "r"((a)[2]), "r"((a)[3]), \
                   "r"(b0v), "r"(b1v))

__device__ __forceinline__ uint32_t sw128(uint32_t off) {
    return off ^ ((off >> 3) & 0x70);
}
// single-instruction packed conversion (cvt.rn.f16x2.f32)
__device__ __forceinline__ uint32_t pack2f(float a, float b) {
    const __half2 h = __float22half2_rn(make_float2(a, b));
    return *(const uint32_t*)&h;
}

// tanh-form GELU using HW tanh (MUFU.TANH, sm_75+):
// gelu(x) ~= 0.5 x (1 + tanh(0.7978845608 (x + 0.044715 x^3)))
// |err vs exact erf-GELU| <= ~3e-4 abs, far below fp16 h-rounding noise.
// Cost: ~5 ALU + 1 MUFU (was ~10 FMA + 2 MUFU).
__device__ __forceinline__ float gelu_tanh(float x) {
    const float s = x * x;
    const float inner = x * fmaf(0.0356774081f, s, 0.7978845608f);
    float th;
    asm("tanh.approx.f32 %0, %1;" : "=f"(th) : "f"(inner));
    return 0.5f * x * (1.f + th);
}

// ------- 1) depthwise 7x7 conv + bias (R10 exact) + fused weight-prep --------
__global__ __launch_bounds__(256) void dwconv_kernel(
    const float* __restrict__ x, const float* __restrict__ cw,
    const float* __restrict__ cb,
    const float* __restrict__ w1, const float* __restrict__ w2)
{
    const int t = threadIdx.x;

    if (blockIdx.x >= Bc*DIM) {               // ---- weight-prep path ----
        const int idx = (blockIdx.x - Bc*DIM) * 256 + t;
        if (idx < HID*DIM) {                  // w1t [n=1024][k=256]
            const int n = idx >> 8, k = idx & 255;
            g_w1t[idx] = __float2half_rn(w1[(size_t)k*HID + n]);
        } else {                              // w2t [n=256][k=1024]
            const int j = idx - HID*DIM;
            const int n = j >> 10, k = j & 1023;
            g_w2t[j] = __float2half_rn(w2[(size_t)k*DIM + n]);
        }
        return;
    }

    const int bc = blockIdx.x;                // b*DIM + c
    const int c  = bc & (DIM-1);

    __shared__ float sx[62][64];              // rows -3..58, cols -3..60
    __shared__ float sw[49];

    const float* xp = x + (size_t)bc*HWc;
    if (t < 49) sw[t] = cw[c*49 + t];

    for (int i = t; i < 62*64; i += 256) {
        const int r = i >> 6, col = i & 63;
        const int gr = r - 3, gc = col - 3;
        float v = 0.f;
        if (gr >= 0 && gr < Hc && gc >= 0 && gc < Wc)
            v = xp[gr*Wc + gc];
        sx[r][col] = v;
    }
    __syncthreads();

    const float bias = cb[c];
    f16* op = g_conv + (size_t)bc*HWc;
    const int col = t & 63, r0 = t >> 6;      // 4 rows x 64 cols per iteration
    if (col < Wc) {
        #pragma unroll
        for (int rr = r0; rr < Hc; rr += 4) {
            float acc = bias;
            #pragma unroll
            for (int ki = 0; ki < 7; ki++)
                #pragma unroll
                for (int kj = 0; kj < 7; kj++)
                    acc = fmaf(sx[rr+ki][col+kj], sw[ki*7+kj], acc);
            op[rr*Wc + col] = __float2half_rn(acc);
        }
    }
}

// ------- 2) LayerNorm over channels + NCHW->NHWC, emit fp16 (R10 exact) ------
__global__ __launch_bounds__(256) void ln_kernel(
    const float* __restrict__ gamma, const float* __restrict__ beta)
{
    int tile = blockIdx.x;
    int b    = tile / (HWc/32);
    int pixbase = (tile % (HWc/32)) * 32;

    __shared__ float s[DIM][33];
    __shared__ float psum[8][32], psq[8][32];
    __shared__ float mu_s[32], rs_s[32];

    int t = threadIdx.x;
    int p = t & 31, gi = t >> 5;

    const f16* base = g_conv + (size_t)b*DIM*HWc + pixbase;
    #pragma unroll
    for (int cc = 0; cc < 32; cc++) {
        int c = gi*32 + cc;
        s[c][p] = __half2float(base[(size_t)c*HWc + p]);
    }
    __syncthreads();

    float sum = 0.f, sq = 0.f;
    #pragma unroll
    for (int cc = 0; cc < 32; cc++) {
        float v = s[gi*32+cc][p];
        sum += v; sq = fmaf(v, v, sq);
    }
    psum[gi][p] = sum; psq[gi][p] = sq;
    __syncthreads();

    if (gi == 0) {
        float S = 0.f, Q = 0.f;
        #pragma unroll
        for (int k = 0; k < 8; k++) { S += psum[k][p]; Q += psq[k][p]; }
        float mu  = S * (1.f/DIM);
        float var = Q * (1.f/DIM) - mu*mu;
        mu_s[p] = mu;
        rs_s[p] = rsqrtf(var + 1e-6f);
    }
    __syncthreads();

    size_t tokbase = (size_t)b*HWc + pixbase;
    for (int i = t; i < 32*128; i += 256) {
        int pp = i >> 7, c2 = (i & 127) * 2;
        float mu = mu_s[pp], rs = rs_s[pp];
        float v0 = (s[c2  ][pp] - mu) * rs * gamma[c2  ] + beta[c2  ];
        float v1 = (s[c2+1][pp] - mu) * rs * gamma[c2+1] + beta[c2+1];
        *(uint32_t*)(g_a + (tokbase + pp)*DIM + c2) = pack2f(v0, v1);
    }
}

// ---------------- 3/4) HMMA fp16 GEMM (R10 exact mainloop) -------------------
#define STAGE  32768
#define GSMEM  (3*STAGE)     // 98304

#define LDSMA(dst, base) do {            \
    LDSM4((dst)[0], (base));             \
    LDSM4((dst)[1], (base) + 2048);      \
    LDSM4((dst)[2], (base) + 4096);      \
    LDSM4((dst)[3], (base) + 6144); } while (0)
#define LDSMB(dst, base) do {            \
    uint32_t _r[4];                      \
    LDSM4(_r, (base));                   \
    (dst)[0][0]=_r[0]; (dst)[0][1]=_r[1]; (dst)[1][0]=_r[2]; (dst)[1][1]=_r[3]; \
    LDSM4(_r, (base) + 2048);            \
    (dst)[2][0]=_r[0]; (dst)[2][1]=_r[1]; (dst)[3][0]=_r[2]; (dst)[3][1]=_r[3]; } while (0)

template<int KTOT, int MODE>
__global__ __launch_bounds__(256, 2) void hgemm_kernel(
    const f16* __restrict__ A, const f16* __restrict__ Bw,
    const float* __restrict__ bias,
    f16* __restrict__ Oh, float* __restrict__ Of)
{
    extern __shared__ char smem[];
    __shared__ float sbias[128];

    const int tid  = threadIdx.x;
    const int wid  = tid >> 5, lane = tid & 31;
    const int warpM = wid >> 2, warpN = wid & 3;        // 2 x 4
    const int n0 = blockIdx.x * 128;
    const size_t m0 = (size_t)blockIdx.y * 128;

    if (tid < 128) sbias[tid] = bias[n0 + tid];

    const uint32_t sb = smem_u32(smem);

    const f16* Abase = A + m0 * KTOT;
    const f16* Bbase = Bw + (size_t)n0 * KTOT;
    const uint32_t soff0 = sw128((uint32_t)((tid >> 3)*128 + (tid & 7)*16));
    const uint32_t goff0 = (uint32_t)(tid >> 3) * (uint32_t)KTOT + (tid & 7)*8;

    auto load_stage = [&](int c, int s) {
        const uint32_t st = sb + s * STAGE + soff0;
        const f16* ga = Abase + goff0 + (uint32_t)c * 64;
        const f16* gb = Bbase + goff0 + (uint32_t)c * 64;
        #pragma unroll
        for (int it = 0; it < 4; it++) {
            CP16(st + it*4096,         ga + it*32*KTOT);
            CP16(st + 16384 + it*4096, gb + it*32*KTOT);
        }
    };

    const int j  = lane >> 3, lr = lane & 7;
    const uint32_t mask = (uint32_t)lr << 4;
    const uint32_t aoff0 = (uint32_t)(warpM*64 + ((j & 1) << 3) + lr)*128
                         + (((uint32_t)(j >> 1) << 4) ^ mask);
    const uint32_t boff0 = 16384
                         + (uint32_t)(warpN*32 + ((j >> 1) << 3) + lr)*128
                         + (((uint32_t)(j & 1) << 4) ^ mask);

    float acc[4][4][4] = {};
    uint32_t ah[2][4][4], bh[2][4][2];

    const int NC = KTOT / 64;
    load_stage(0, 0); CP_COMMIT();
    if (NC > 1) { load_stage(1, 1); CP_COMMIT(); }

    int s_use = 0, s_load = 2;
    #pragma unroll 1
    for (int c = 0; c < NC; c++) {
        if (c + 1 < NC) { CP_WAIT(1); } else { CP_WAIT(0); }
        __syncthreads();

        const uint32_t st = sb + s_use * STAGE;
        if (++s_use == 3) s_use = 0;
        const uint32_t a0 = st + aoff0, b0 = st + boff0;

        LDSMB(bh[0], b0);
        LDSMA(ah[0], a0);
        if (c + 2 < NC) {
            load_stage(c + 2, s_load); CP_COMMIT();
            if (++s_load == 3) s_load = 0;
        }

        #pragma unroll
        for (int ks = 0; ks < 4; ks++) {
            const int cur = ks & 1, nxt = cur ^ 1;
            if (ks < 3) {
                const uint32_t kx = 32u * (ks + 1);
                LDSMB(bh[nxt], b0 ^ kx);
                LDSMA(ah[nxt], a0 ^ kx);
            }
            #pragma unroll
            for (int mt = 0; mt < 4; mt++)
                #pragma unroll
                for (int nt = 0; nt < 4; nt++)
                    MMA16816(acc[mt][nt], ah[cur][mt],
                             bh[cur][nt][0], bh[cur][nt][1]);
        }
    }

    const int mlane = lane >> 2;
    const int nlane = (lane & 3) * 2;

    if (MODE == 1) {
        #pragma unroll
        for (int mt = 0; mt < 4; mt++) {
            const size_t mA = m0 + warpM*64 + mt*16 + mlane;
            #pragma unroll
            for (int nt = 0; nt < 4; nt++) {
                const int nc = warpN*32 + nt*8 + nlane;
                const float b0 = sbias[nc], b1 = sbias[nc + 1];
                #pragma unroll
                for (int half = 0; half < 2; half++) {
                    float v0 = gelu_tanh(acc[mt][nt][half*2]     + b0);
                    float v1 = gelu_tanh(acc[mt][nt][half*2 + 1] + b1);
                    size_t o = (mA + half*8) * (size_t)HID + n0 + nc;
                    *(uint32_t*)(Oh + o) = pack2f(v0, v1);
                }
            }
        }
    } else {
        __syncthreads();
        float* sf = (float*)smem;          // [128 n][132 m]
        #pragma unroll
        for (int mt = 0; mt < 4; mt++) {
            const int mA = warpM*64 + mt*16 + mlane;
            #pragma unroll
            for (int nt = 0; nt < 4; nt++) {
                const int nc = warpN*32 + nt*8 + nlane;
                sf[(nc    )*132 + mA    ] = acc[mt][nt][0];
                sf[(nc + 1)*132 + mA    ] = acc[mt][nt][1];
                sf[(nc    )*132 + mA + 8] = acc[mt][nt][2];
                sf[(nc + 1)*132 + mA + 8] = acc[mt][nt][3];
            }
        }
        __syncthreads();
        #pragma unroll 4
        for (int i = tid; i < 128*128; i += 256) {
            const int n = i >> 7, mm = i & 127;
            const int tok = (int)m0 + mm;
            const int b = tok / HWc, pix = tok % HWc;
            Of[((size_t)b*DIM + n0 + n)*HWc + pix] = sf[n*132 + mm] + sbias[n];
        }
    }
}

// ---------------- launch -----------------------------------------------------
extern "C" void kernel_launch(void* const* d_in, const int* in_sizes, int n_in,
                              void* d_out, int out_size)
{
    const float* x      = (const float*)d_in[0];
    const float* conv_w = (const float*)d_in[1];
    const float* conv_b = (const float*)d_in[2];
    const float* ln_g   = (const float*)d_in[3];
    const float* ln_b   = (const float*)d_in[4];
    const float* w1     = (const float*)d_in[5];
    const float* b1     = (const float*)d_in[6];
    const float* w2     = (const float*)d_in[7];
    const float* b2     = (const float*)d_in[8];
    float* out = (float*)d_out;

    f16 *p_a, *p_h, *p_w1t, *p_w2t;
    cudaGetSymbolAddress((void**)&p_a,   g_a);
    cudaGetSymbolAddress((void**)&p_h,   g_h);
    cudaGetSymbolAddress((void**)&p_w1t, g_w1t);
    cudaGetSymbolAddress((void**)&p_w2t, g_w2t);

    cudaFuncSetAttribute((const void*)hgemm_kernel<DIM, 1>,
                         cudaFuncAttributeMaxDynamicSharedMemorySize, GSMEM);
    cudaFuncSetAttribute((const void*)hgemm_kernel<HID, 2>,
                         cudaFuncAttributeMaxDynamicSharedMemorySize, GSMEM);

    // conv (8192 blocks) + fused weight-prep (2048 blocks)
    dwconv_kernel<<<Bc*DIM + (2*HID*DIM)/256, 256>>>(x, conv_w, conv_b, w1, w2);
    ln_kernel<<<TOK/32, 256>>>(ln_g, ln_b);

    // GEMM1: [TOK,256] x w1t -> tanh-GELU -> h (fp16)
    hgemm_kernel<DIM, 1><<<dim3(HID/128, TOK/128), 256, GSMEM>>>(
        p_a, p_w1t, b1, p_h, nullptr);
    // GEMM2: [TOK,1024] x w2t -> +b2 -> fp32 NCHW out
    hgemm_kernel<HID, 2><<<dim3(DIM/128, TOK/128), 256, GSMEM>>>(
        p_h, p_w2t, b2, nullptr, out);
}

// round 16
// speedup vs baseline: 1.3341x; 1.1184x over previous
#include <cuda_runtime.h>
#include <cuda_fp16.h>
#include <math.h>
#include <stdint.h>

#define Bc   32
#define DIM  256
#define Hc   56
#define Wc   56
#define HWc  (Hc*Wc)          // 3136
#define TOK  (Bc*HWc)         // 100352
#define HID  1024

typedef __half f16;

// ---------------- scratch (device globals; no runtime allocation) ------------
__device__ __align__(256) f16 g_conv[(size_t)Bc*DIM*HWc];    // conv out, NCHW f16
__device__ __align__(256) f16 g_a  [(size_t)TOK*DIM];        // LN out (fp16)
__device__ __align__(256) f16 g_h  [(size_t)TOK*HID];        // hidden (fp16)
__device__ __align__(256) f16 g_w1t[(size_t)HID*DIM];        // w1^T [N=1024][K=256]
__device__ __align__(256) f16 g_w2t[(size_t)DIM*HID];        // w2^T [N=256][K=1024]

// ---------------- asm primitives (base sm_103, no 'a' features) --------------
__device__ __forceinline__ uint32_t smem_u32(const void* p) {
    uint32_t a;
    asm("{ .reg .u64 t; cvta.to.shared.u64 t, %1; cvt.u32.u64 %0, t; }"
        : "=r"(a) : "l"(p));
    return a;
}
#define CP16(dst, src) \
    asm volatile("cp.async.cg.shared.global [%0], [%1], 16;" \
                 :: "r"(dst), "l"(src) : "memory")
#define CP_COMMIT() asm volatile("cp.async.commit_group;" ::: "memory")
#define CP_WAIT(n)  asm volatile("cp.async.wait_group %0;" :: "n"(n) : "memory")
#define LDSM4(r, addr) \
    asm volatile("ldmatrix.sync.aligned.m8n8.x4.shared.b16 {%0,%1,%2,%3}, [%4];" \
                 : "=r"((r)[0]), "=r"((r)[1]), "=r"((r)[2]), "=r"((r)[3]) \
                 : "r"(addr))
#define MMA16816(d, a, b0v, b1v) \
    asm volatile("mma.sync.aligned.m16n8k16.row.col.f32.f16.f16.f32 " \
                 "{%0,%1,%2,%3}, {%4,%5,%6,%7}, {%8,%9}, {%0,%1,%2,%3};" \
                 : "+f"((d)[0]), "+f"((d)[1]), "+f"((d)[2]), "+f"((d)[3]) \
                 : "r"((a)[0]), "r"((a)[1]), "r"((a)[2]), "r"((a)[3]), \
                   "r"(b0v), "r"(b1v))

__device__ __forceinline__ uint32_t sw128(uint32_t off) {
    return off ^ ((off >> 3) & 0x70);
}
// single-instruction packed conversion (cvt.rn.f16x2.f32)
__device__ __forceinline__ uint32_t pack2f(float a, float b) {
    const __half2 h = __float22half2_rn(make_float2(a, b));
    return *(const uint32_t*)&h;
}

// tanh-form GELU using HW tanh (MUFU.TANH, sm_75+).
__device__ __forceinline__ float gelu_tanh(float x) {
    const float s = x * x;
    const float inner = x * fmaf(0.0356774081f, s, 0.7978845608f);
    float th;
    asm("tanh.approx.f32 %0, %1;" : "=f"(th) : "f"(inner));
    return 0.5f * x * (1.f + th);
}

// ------- 1) depthwise 7x7 conv + bias + fused weight-prep --------------------
// Blocks [0, Bc*DIM): conv, one block per (b,c) plane.
//   Compute: 224 active threads = 28 column-pairs x 8 row-groups(7 rows).
//   Window rows loaded as 4x LDS.64 (8 floats) feeding TWO adjacent-column
//   accumulators: 14 LDS-instr/output vs 49. Weights in registers.
//   FMA order per accumulator identical to R10 -> bit-identical output.
// Blocks [Bc*DIM, +2048): transpose w1/w2 to fp16 (fused prep).
__global__ __launch_bounds__(256) void dwconv_kernel(
    const float* __restrict__ x, const float* __restrict__ cw,
    const float* __restrict__ cb,
    const float* __restrict__ w1, const float* __restrict__ w2)
{
    const int t = threadIdx.x;

    if (blockIdx.x >= Bc*DIM) {               // ---- weight-prep path ----
        const int idx = (blockIdx.x - Bc*DIM) * 256 + t;
        if (idx < HID*DIM) {                  // w1t [n=1024][k=256]
            const int n = idx >> 8, k = idx & 255;
            g_w1t[idx] = __float2half_rn(w1[(size_t)k*HID + n]);
        } else {                              // w2t [n=256][k=1024]
            const int j = idx - HID*DIM;
            const int n = j >> 10, k = j & 1023;
            g_w2t[j] = __float2half_rn(w2[(size_t)k*DIM + n]);
        }
        return;
    }

    const int bc = blockIdx.x;                // b*DIM + c
    const int c  = bc & (DIM-1);

    __shared__ float sx[62][64];              // rows -3..58, cols -3..60
    __shared__ float sw[49];

    const float* xp = x + (size_t)bc*HWc;
    if (t < 49) sw[t] = cw[c*49 + t];

    for (int i = t; i < 62*64; i += 256) {
        const int r = i >> 6, col = i & 63;
        const int gr = r - 3, gc = col - 3;
        float v = 0.f;
        if (gr >= 0 && gr < Hc && gc >= 0 && gc < Wc)
            v = xp[gr*Wc + gc];
        sx[r][col] = v;
    }
    __syncthreads();

    if (t < 224) {
        const int col0 = (t % 28) * 2;        // even -> float2-aligned in sx
        const int r0   = (t / 28) * 7;        // 7 consecutive output rows

        float w[49];
        #pragma unroll
        for (int i = 0; i < 49; i++) w[i] = sw[i];
        const float bias = cb[c];

        f16* op = g_conv + (size_t)bc*HWc;
        #pragma unroll
        for (int rr = 0; rr < 7; rr++) {
            const int row = r0 + rr;
            float acc0 = bias, acc1 = bias;
            #pragma unroll
            for (int ki = 0; ki < 7; ki++) {
                const float2* rp = (const float2*)&sx[row + ki][col0];
                const float2 f0 = rp[0], f1 = rp[1], f2 = rp[2], f3 = rp[3];
                const float f[8] = { f0.x, f0.y, f1.x, f1.y,
                                     f2.x, f2.y, f3.x, f3.y };
                #pragma unroll
                for (int kj = 0; kj < 7; kj++) {
                    acc0 = fmaf(f[kj],     w[ki*7 + kj], acc0);
                    acc1 = fmaf(f[kj + 1], w[ki*7 + kj], acc1);
                }
            }
            *(uint32_t*)(op + row*Wc + col0) = pack2f(acc0, acc1);
        }
    }
}

// ------- 2) LayerNorm over channels + NCHW->NHWC, emit fp16 (R10 exact) ------
__global__ __launch_bounds__(256) void ln_kernel(
    const float* __restrict__ gamma, const float* __restrict__ beta)
{
    int tile = blockIdx.x;
    int b    = tile / (HWc/32);
    int pixbase = (tile % (HWc/32)) * 32;

    __shared__ float s[DIM][33];
    __shared__ float psum[8][32], psq[8][32];
    __shared__ float mu_s[32], rs_s[32];

    int t = threadIdx.x;
    int p = t & 31, gi = t >> 5;

    const f16* base = g_conv + (size_t)b*DIM*HWc + pixbase;
    #pragma unroll
    for (int cc = 0; cc < 32; cc++) {
        int c = gi*32 + cc;
        s[c][p] = __half2float(base[(size_t)c*HWc + p]);
    }
    __syncthreads();

    float sum = 0.f, sq = 0.f;
    #pragma unroll
    for (int cc = 0; cc < 32; cc++) {
        float v = s[gi*32+cc][p];
        sum += v; sq = fmaf(v, v, sq);
    }
    psum[gi][p] = sum; psq[gi][p] = sq;
    __syncthreads();

    if (gi == 0) {
        float S = 0.f, Q = 0.f;
        #pragma unroll
        for (int k = 0; k < 8; k++) { S += psum[k][p]; Q += psq[k][p]; }
        float mu  = S * (1.f/DIM);
        float var = Q * (1.f/DIM) - mu*mu;
        mu_s[p] = mu;
        rs_s[p] = rsqrtf(var + 1e-6f);
    }
    __syncthreads();

    size_t tokbase = (size_t)b*HWc + pixbase;
    for (int i = t; i < 32*128; i += 256) {
        int pp = i >> 7, c2 = (i & 127) * 2;
        float mu = mu_s[pp], rs = rs_s[pp];
        float v0 = (s[c2  ][pp] - mu) * rs * gamma[c2  ] + beta[c2  ];
        float v1 = (s[c2+1][pp] - mu) * rs * gamma[c2+1] + beta[c2+1];
        *(uint32_t*)(g_a + (tokbase + pp)*DIM + c2) = pack2f(v0, v1);
    }
}

// ---------------- 3/4) HMMA fp16 GEMM (R10 exact mainloop) -------------------
#define STAGE  32768
#define GSMEM  (3*STAGE)     // 98304

#define LDSMA(dst, base) do {            \
    LDSM4((dst)[0], (base));             \
    LDSM4((dst)[1], (base) + 2048);      \
    LDSM4((dst)[2], (base) + 4096);      \
    LDSM4((dst)[3], (base) + 6144); } while (0)
#define LDSMB(dst, base) do {            \
    uint32_t _r[4];                      \
    LDSM4(_r, (base));                   \
    (dst)[0][0]=_r[0]; (dst)[0][1]=_r[1]; (dst)[1][0]=_r[2]; (dst)[1][1]=_r[3]; \
    LDSM4(_r, (base) + 2048);            \
    (dst)[2][0]=_r[0]; (dst)[2][1]=_r[1]; (dst)[3][0]=_r[2]; (dst)[3][1]=_r[3]; } while (0)

template<int KTOT, int MODE>
__global__ __launch_bounds__(256, 2) void hgemm_kernel(
    const f16* __restrict__ A, const f16* __restrict__ Bw,
    const float* __restrict__ bias,
    f16* __restrict__ Oh, float* __restrict__ Of)
{
    extern __shared__ char smem[];
    __shared__ float sbias[128];

    const int tid  = threadIdx.x;
    const int wid  = tid >> 5, lane = tid & 31;
    const int warpM = wid >> 2, warpN = wid & 3;        // 2 x 4
    const int n0 = blockIdx.x * 128;
    const size_t m0 = (size_t)blockIdx.y * 128;

    if (tid < 128) sbias[tid] = bias[n0 + tid];

    const uint32_t sb = smem_u32(smem);

    const f16* Abase = A + m0 * KTOT;
    const f16* Bbase = Bw + (size_t)n0 * KTOT;
    const uint32_t soff0 = sw128((uint32_t)((tid >> 3)*128 + (tid & 7)*16));
    const uint32_t goff0 = (uint32_t)(tid >> 3) * (uint32_t)KTOT + (tid & 7)*8;

    auto load_stage = [&](int c, int s) {
        const uint32_t st = sb + s * STAGE + soff0;
        const f16* ga = Abase + goff0 + (uint32_t)c * 64;
        const f16* gb = Bbase + goff0 + (uint32_t)c * 64;
        #pragma unroll
        for (int it = 0; it < 4; it++) {
            CP16(st + it*4096,         ga + it*32*KTOT);
            CP16(st + 16384 + it*4096, gb + it*32*KTOT);
        }
    };

    const int j  = lane >> 3, lr = lane & 7;
    const uint32_t mask = (uint32_t)lr << 4;
    const uint32_t aoff0 = (uint32_t)(warpM*64 + ((j & 1) << 3) + lr)*128
                         + (((uint32_t)(j >> 1) << 4) ^ mask);
    const uint32_t boff0 = 16384
                         + (uint32_t)(warpN*32 + ((j >> 1) << 3) + lr)*128
                         + (((uint32_t)(j & 1) << 4) ^ mask);

    float acc[4][4][4] = {};
    uint32_t ah[2][4][4], bh[2][4][2];

    const int NC = KTOT / 64;
    load_stage(0, 0); CP_COMMIT();
    if (NC > 1) { load_stage(1, 1); CP_COMMIT(); }

    int s_use = 0, s_load = 2;
    #pragma unroll 1
    for (int c = 0; c < NC; c++) {
        if (c + 1 < NC) { CP_WAIT(1); } else { CP_WAIT(0); }
        __syncthreads();

        const uint32_t st = sb + s_use * STAGE;
        if (++s_use == 3) s_use = 0;
        const uint32_t a0 = st + aoff0, b0 = st + boff0;

        LDSMB(bh[0], b0);
        LDSMA(ah[0], a0);
        if (c + 2 < NC) {
            load_stage(c + 2, s_load); CP_COMMIT();
            if (++s_load == 3) s_load = 0;
        }

        #pragma unroll
        for (int ks = 0; ks < 4; ks++) {
            const int cur = ks & 1, nxt = cur ^ 1;
            if (ks < 3) {
                const uint32_t kx = 32u * (ks + 1);
                LDSMB(bh[nxt], b0 ^ kx);
                LDSMA(ah[nxt], a0 ^ kx);
            }
            #pragma unroll
            for (int mt = 0; mt < 4; mt++)
                #pragma unroll
                for (int nt = 0; nt < 4; nt++)
                    MMA16816(acc[mt][nt], ah[cur][mt],
                             bh[cur][nt][0], bh[cur][nt][1]);
        }
    }

    const int mlane = lane >> 2;
    const int nlane = (lane & 3) * 2;

    if (MODE == 1) {
        #pragma unroll
        for (int mt = 0; mt < 4; mt++) {
            const size_t mA = m0 + warpM*64 + mt*16 + mlane;
            #pragma unroll
            for (int nt = 0; nt < 4; nt++) {
                const int nc = warpN*32 + nt*8 + nlane;
                const float b0 = sbias[nc], b1 = sbias[nc + 1];
                #pragma unroll
                for (int half = 0; half < 2; half++) {
                    float v0 = gelu_tanh(acc[mt][nt][half*2]     + b0);
                    float v1 = gelu_tanh(acc[mt][nt][half*2 + 1] + b1);
                    size_t o = (mA + half*8) * (size_t)HID + n0 + nc;
                    *(uint32_t*)(Oh + o) = pack2f(v0, v1);
                }
            }
        }
    } else {
        __syncthreads();
        float* sf = (float*)smem;          // [128 n][132 m]
        #pragma unroll
        for (int mt = 0; mt < 4; mt++) {
            const int mA = warpM*64 + mt*16 + mlane;
            #pragma unroll
            for (int nt = 0; nt < 4; nt++) {
                const int nc = warpN*32 + nt*8 + nlane;
                sf[(nc    )*132 + mA    ] = acc[mt][nt][0];
                sf[(nc + 1)*132 + mA    ] = acc[mt][nt][1];
                sf[(nc    )*132 + mA + 8] = acc[mt][nt][2];
                sf[(nc + 1)*132 + mA + 8] = acc[mt][nt][3];
            }
        }
        __syncthreads();
        #pragma unroll 4
        for (int i = tid; i < 128*128; i += 256) {
            const int n = i >> 7, mm = i & 127;
            const int tok = (int)m0 + mm;
            const int b = tok / HWc, pix = tok % HWc;
            Of[((size_t)b*DIM + n0 + n)*HWc + pix] = sf[n*132 + mm] + sbias[n];
        }
    }
}

// ---------------- launch -----------------------------------------------------
extern "C" void kernel_launch(void* const* d_in, const int* in_sizes, int n_in,
                              void* d_out, int out_size)
{
    const float* x      = (const float*)d_in[0];
    const float* conv_w = (const float*)d_in[1];
    const float* conv_b = (const float*)d_in[2];
    const float* ln_g   = (const float*)d_in[3];
    const float* ln_b   = (const float*)d_in[4];
    const float* w1     = (const float*)d_in[5];
    const float* b1     = (const float*)d_in[6];
    const float* w2     = (const float*)d_in[7];
    const float* b2     = (const float*)d_in[8];
    float* out = (float*)d_out;

    f16 *p_a, *p_h, *p_w1t, *p_w2t;
    cudaGetSymbolAddress((void**)&p_a,   g_a);
    cudaGetSymbolAddress((void**)&p_h,   g_h);
    cudaGetSymbolAddress((void**)&p_w1t, g_w1t);
    cudaGetSymbolAddress((void**)&p_w2t, g_w2t);

    cudaFuncSetAttribute((const void*)hgemm_kernel<DIM, 1>,
                         cudaFuncAttributeMaxDynamicSharedMemorySize, GSMEM);
    cudaFuncSetAttribute((const void*)hgemm_kernel<HID, 2>,
                         cudaFuncAttributeMaxDynamicSharedMemorySize, GSMEM);

    // conv (8192 blocks) + fused weight-prep (2048 blocks)
    dwconv_kernel<<<Bc*DIM + (2*HID*DIM)/256, 256>>>(x, conv_w, conv_b, w1, w2);
    ln_kernel<<<TOK/32, 256>>>(ln_g, ln_b);

    // GEMM1: [TOK,256] x w1t -> tanh-GELU -> h (fp16)
    hgemm_kernel<DIM, 1><<<dim3(HID/128, TOK/128), 256, GSMEM>>>(
        p_a, p_w1t, b1, p_h, nullptr);
    // GEMM2: [TOK,1024] x w2t -> +b2 -> fp32 NCHW out
    hgemm_kernel<HID, 2><<<dim3(DIM/128, TOK/128), 256, GSMEM>>>(
        p_h, p_w2t, b2, nullptr, out);
}

// round 17
// speedup vs baseline: 1.3678x; 1.0253x over previous
#include <cuda_runtime.h>
#include <cuda_fp16.h>
#include <math.h>
#include <stdint.h>

#define Bc   32
#define DIM  256
#define Hc   56
#define Wc   56
#define HWc  (Hc*Wc)          // 3136
#define TOK  (Bc*HWc)         // 100352
#define HID  1024

typedef __half f16;

// ---------------- scratch (device globals; no runtime allocation) ------------
__device__ __align__(256) f16 g_conv[(size_t)Bc*DIM*HWc];    // conv out, NCHW f16
__device__ __align__(256) f16 g_a  [(size_t)TOK*DIM];        // LN out (fp16)
__device__ __align__(256) f16 g_h  [(size_t)TOK*HID];        // hidden (fp16)
__device__ __align__(256) f16 g_w1t[(size_t)HID*DIM];        // w1^T [N=1024][K=256]
__device__ __align__(256) f16 g_w2t[(size_t)DIM*HID];        // w2^T [N=256][K=1024]

// ---------------- asm primitives (base sm_103, no 'a' features) --------------
__device__ __forceinline__ uint32_t smem_u32(const void* p) {
    uint32_t a;
    asm("{ .reg .u64 t; cvta.to.shared.u64 t, %1; cvt.u32.u64 %0, t; }"
        : "=r"(a) : "l"(p));
    return a;
}
#define CP16(dst, src) \
    asm volatile("cp.async.cg.shared.global [%0], [%1], 16;" \
                 :: "r"(dst), "l"(src) : "memory")
#define CP_COMMIT() asm volatile("cp.async.commit_group;" ::: "memory")
#define CP_WAIT(n)  asm volatile("cp.async.wait_group %0;" :: "n"(n) : "memory")
#define LDSM4(r, addr) \
    asm volatile("ldmatrix.sync.aligned.m8n8.x4.shared.b16 {%0,%1,%2,%3}, [%4];" \
                 : "=r"((r)[0]), "=r"((r)[1]), "=r"((r)[2]), "=r"((r)[3]) \
                 : "r"(addr))
#define MMA16816(d, a, b0v, b1v) \
    asm volatile("mma.sync.aligned.m16n8k16.row.col.f32.f16.f16.f32 " \
                 "{%0,%1,%2,%3}, {%4,%5,%6,%7}, {%8,%9}, {%0,%1,%2,%3};" \
                 : "+f"((d)[0]), "+f"((d)[1]), "+f"((d)[2]), "+f"((d)[3]) \
                 : "r"((a)[0]), "r"((a)[1]), "r"((a)[2]), "r"((a)[3]), \
                   "r"(b0v), "r"(b1v))

__device__ __forceinline__ uint32_t sw128(uint32_t off) {
    return off ^ ((off >> 3) & 0x70);
}
// single-instruction packed conversion (cvt.rn.f16x2.f32)
__device__ __forceinline__ uint32_t pack2f(float a, float b) {
    const __half2 h = __float22half2_rn(make_float2(a, b));
    return *(const uint32_t*)&h;
}

// tanh-form GELU using HW tanh (MUFU.TANH, sm_75+).
__device__ __forceinline__ float gelu_tanh(float x) {
    const float s = x * x;
    const float inner = x * fmaf(0.0356774081f, s, 0.7978845608f);
    float th;
    asm("tanh.approx.f32 %0, %1;" : "=f"(th) : "f"(inner));
    return 0.5f * x * (1.f + th);
}

// ------- 1) depthwise 7x7 conv + bias + fused weight-prep (R16 exact) --------
__global__ __launch_bounds__(256) void dwconv_kernel(
    const float* __restrict__ x, const float* __restrict__ cw,
    const float* __restrict__ cb,
    const float* __restrict__ w1, const float* __restrict__ w2)
{
    const int t = threadIdx.x;

    if (blockIdx.x >= Bc*DIM) {               // ---- weight-prep path ----
        const int idx = (blockIdx.x - Bc*DIM) * 256 + t;
        if (idx < HID*DIM) {                  // w1t [n=1024][k=256]
            const int n = idx >> 8, k = idx & 255;
            g_w1t[idx] = __float2half_rn(w1[(size_t)k*HID + n]);
        } else {                              // w2t [n=256][k=1024]
            const int j = idx - HID*DIM;
            const int n = j >> 10, k = j & 1023;
            g_w2t[j] = __float2half_rn(w2[(size_t)k*DIM + n]);
        }
        return;
    }

    const int bc = blockIdx.x;                // b*DIM + c
    const int c  = bc & (DIM-1);

    __shared__ float sx[62][64];              // rows -3..58, cols -3..60
    __shared__ float sw[49];

    const float* xp = x + (size_t)bc*HWc;
    if (t < 49) sw[t] = cw[c*49 + t];

    for (int i = t; i < 62*64; i += 256) {
        const int r = i >> 6, col = i & 63;
        const int gr = r - 3, gc = col - 3;
        float v = 0.f;
        if (gr >= 0 && gr < Hc && gc >= 0 && gc < Wc)
            v = xp[gr*Wc + gc];
        sx[r][col] = v;
    }
    __syncthreads();

    if (t < 224) {
        const int col0 = (t % 28) * 2;        // even -> float2-aligned in sx
        const int r0   = (t / 28) * 7;        // 7 consecutive output rows

        float w[49];
        #pragma unroll
        for (int i = 0; i < 49; i++) w[i] = sw[i];
        const float bias = cb[c];

        f16* op = g_conv + (size_t)bc*HWc;
        #pragma unroll
        for (int rr = 0; rr < 7; rr++) {
            const int row = r0 + rr;
            float acc0 = bias, acc1 = bias;
            #pragma unroll
            for (int ki = 0; ki < 7; ki++) {
                const float2* rp = (const float2*)&sx[row + ki][col0];
                const float2 f0 = rp[0], f1 = rp[1], f2 = rp[2], f3 = rp[3];
                const float f[8] = { f0.x, f0.y, f1.x, f1.y,
                                     f2.x, f2.y, f3.x, f3.y };
                #pragma unroll
                for (int kj = 0; kj < 7; kj++) {
                    acc0 = fmaf(f[kj],     w[ki*7 + kj], acc0);
                    acc1 = fmaf(f[kj + 1], w[ki*7 + kj], acc1);
                }
            }
            *(uint32_t*)(op + row*Wc + col0) = pack2f(acc0, acc1);
        }
    }
}

// ------- 2) LayerNorm: 64-pixel tiles, half2 full-width loads -----------------
// Per-pixel FP sum order identical to the 32-pixel version -> bit-identical.
__global__ __launch_bounds__(256) void ln_kernel(
    const float* __restrict__ gamma, const float* __restrict__ beta)
{
    const int tile = blockIdx.x;                  // 64 pixels per block
    const int b    = tile / (HWc/64);
    const int pixbase = (tile % (HWc/64)) * 64;

    __shared__ uint32_t s2[DIM][33];              // half2: pixels (2p, 2p+1)
    __shared__ float ps0[8][32], ps1[8][32], pq0[8][32], pq1[8][32];
    __shared__ float mu_s[64], rs_s[64];

    const int t = threadIdx.x;
    const int p = t & 31, gi = t >> 5;

    const f16* base = g_conv + (size_t)b*DIM*HWc + pixbase;
    float s0 = 0.f, s1 = 0.f, q0 = 0.f, q1 = 0.f;
    #pragma unroll
    for (int cc = 0; cc < 32; cc++) {
        const int c = gi*32 + cc;
        const uint32_t v = *(const uint32_t*)(base + (size_t)c*HWc + 2*p);
        s2[c][p] = v;
        const __half2 h2 = *(const __half2*)&v;
        const float f0 = __low2float(h2), f1 = __high2float(h2);
        s0 += f0; q0 = fmaf(f0, f0, q0);
        s1 += f1; q1 = fmaf(f1, f1, q1);
    }
    ps0[gi][p] = s0; ps1[gi][p] = s1;
    pq0[gi][p] = q0; pq1[gi][p] = q1;
    __syncthreads();

    if (gi == 0) {
        float S0 = 0.f, S1 = 0.f, Q0 = 0.f, Q1 = 0.f;
        #pragma unroll
        for (int k = 0; k < 8; k++) {
            S0 += ps0[k][p]; S1 += ps1[k][p];
            Q0 += pq0[k][p]; Q1 += pq1[k][p];
        }
        const float mu0 = S0 * (1.f/DIM), mu1 = S1 * (1.f/DIM);
        mu_s[2*p    ] = mu0;
        rs_s[2*p    ] = rsqrtf(Q0*(1.f/DIM) - mu0*mu0 + 1e-6f);
        mu_s[2*p + 1] = mu1;
        rs_s[2*p + 1] = rsqrtf(Q1*(1.f/DIM) - mu1*mu1 + 1e-6f);
    }
    __syncthreads();

    const size_t tokbase = (size_t)b*HWc + pixbase;
    for (int i = t; i < 64*128; i += 256) {
        const int pp = i >> 7, c2 = (i & 127) * 2;
        const uint32_t v0 = s2[c2][pp >> 1], v1 = s2[c2 + 1][pp >> 1];
        const __half2 h0 = *(const __half2*)&v0, h1 = *(const __half2*)&v1;
        const float f0 = (pp & 1) ? __high2float(h0) : __low2float(h0);
        const float f1 = (pp & 1) ? __high2float(h1) : __low2float(h1);
        const float mu = mu_s[pp], rs = rs_s[pp];
        const float o0 = (f0 - mu) * rs * gamma[c2    ] + beta[c2    ];
        const float o1 = (f1 - mu) * rs * gamma[c2 + 1] + beta[c2 + 1];
        *(uint32_t*)(g_a + (tokbase + pp)*DIM + c2) = pack2f(o0, o1);
    }
}

// ---------------- 3/4) HMMA fp16 GEMM (R10 exact mainloop) -------------------
#define STAGE  32768
#define GSMEM  (3*STAGE)     // 98304

#define LDSMA(dst, base) do {            \
    LDSM4((dst)[0], (base));             \
    LDSM4((dst)[1], (base) + 2048);      \
    LDSM4((dst)[2], (base) + 4096);      \
    LDSM4((dst)[3], (base) + 6144); } while (0)
#define LDSMB(dst, base) do {            \
    uint32_t _r[4];                      \
    LDSM4(_r, (base));                   \
    (dst)[0][0]=_r[0]; (dst)[0][1]=_r[1]; (dst)[1][0]=_r[2]; (dst)[1][1]=_r[3]; \
    LDSM4(_r, (base) + 2048);            \
    (dst)[2][0]=_r[0]; (dst)[2][1]=_r[1]; (dst)[3][0]=_r[2]; (dst)[3][1]=_r[3]; } while (0)

template<int KTOT, int MODE>
__global__ __launch_bounds__(256, 2) void hgemm_kernel(
    const f16* __restrict__ A, const f16* __restrict__ Bw,
    const float* __restrict__ bias,
    f16* __restrict__ Oh, float* __restrict__ Of)
{
    extern __shared__ char smem[];
    __shared__ float sbias[128];

    const int tid  = threadIdx.x;
    const int wid  = tid >> 5, lane = tid & 31;
    const int warpM = wid >> 2, warpN = wid & 3;        // 2 x 4
    const int n0 = blockIdx.x * 128;
    const size_t m0 = (size_t)blockIdx.y * 128;

    if (tid < 128) sbias[tid] = bias[n0 + tid];

    const uint32_t sb = smem_u32(smem);

    const f16* Abase = A + m0 * KTOT;
    const f16* Bbase = Bw + (size_t)n0 * KTOT;
    const uint32_t soff0 = sw128((uint32_t)((tid >> 3)*128 + (tid & 7)*16));
    const uint32_t goff0 = (uint32_t)(tid >> 3) * (uint32_t)KTOT + (tid & 7)*8;

    auto load_stage = [&](int c, int s) {
        const uint32_t st = sb + s * STAGE + soff0;
        const f16* ga = Abase + goff0 + (uint32_t)c * 64;
        const f16* gb = Bbase + goff0 + (uint32_t)c * 64;
        #pragma unroll
        for (int it = 0; it < 4; it++) {
            CP16(st + it*4096,         ga + it*32*KTOT);
            CP16(st + 16384 + it*4096, gb + it*32*KTOT);
        }
    };

    const int j  = lane >> 3, lr = lane & 7;
    const uint32_t mask = (uint32_t)lr << 4;
    const uint32_t aoff0 = (uint32_t)(warpM*64 + ((j & 1) << 3) + lr)*128
                         + (((uint32_t)(j >> 1) << 4) ^ mask);
    const uint32_t boff0 = 16384
                         + (uint32_t)(warpN*32 + ((j >> 1) << 3) + lr)*128
                         + (((uint32_t)(j & 1) << 4) ^ mask);

    float acc[4][4][4] = {};
    uint32_t ah[2][4][4], bh[2][4][2];

    const int NC = KTOT / 64;
    load_stage(0, 0); CP_COMMIT();
    if (NC > 1) { load_stage(1, 1); CP_COMMIT(); }

    int s_use = 0, s_load = 2;
    #pragma unroll 1
    for (int c = 0; c < NC; c++) {
        if (c + 1 < NC) { CP_WAIT(1); } else { CP_WAIT(0); }
        __syncthreads();

        const uint32_t st = sb + s_use * STAGE;
        if (++s_use == 3) s_use = 0;
        const uint32_t a0 = st + aoff0, b0 = st + boff0;

        LDSMB(bh[0], b0);
        LDSMA(ah[0], a0);
        if (c + 2 < NC) {
            load_stage(c + 2, s_load); CP_COMMIT();
            if (++s_load == 3) s_load = 0;
        }

        #pragma unroll
        for (int ks = 0; ks < 4; ks++) {
            const int cur = ks & 1, nxt = cur ^ 1;
            if (ks < 3) {
                const uint32_t kx = 32u * (ks + 1);
                LDSMB(bh[nxt], b0 ^ kx);
                LDSMA(ah[nxt], a0 ^ kx);
            }
            #pragma unroll
            for (int mt = 0; mt < 4; mt++)
                #pragma unroll
                for (int nt = 0; nt < 4; nt++)
                    MMA16816(acc[mt][nt], ah[cur][mt],
                             bh[cur][nt][0], bh[cur][nt][1]);
        }
    }

    const int mlane = lane >> 2;
    const int nlane = (lane & 3) * 2;

    if (MODE == 1) {
        #pragma unroll
        for (int mt = 0; mt < 4; mt++) {
            const size_t mA = m0 + warpM*64 + mt*16 + mlane;
            #pragma unroll
            for (int nt = 0; nt < 4; nt++) {
                const int nc = warpN*32 + nt*8 + nlane;
                const float b0 = sbias[nc], b1 = sbias[nc + 1];
                #pragma unroll
                for (int half = 0; half < 2; half++) {
                    float v0 = gelu_tanh(acc[mt][nt][half*2]     + b0);
                    float v1 = gelu_tanh(acc[mt][nt][half*2 + 1] + b1);
                    size_t o = (mA + half*8) * (size_t)HID + n0 + nc;
                    *(uint32_t*)(Oh + o) = pack2f(v0, v1);
                }
            }
        }
    } else {
        __syncthreads();
        float* sf = (float*)smem;          // [128 n][132 m]
        #pragma unroll
        for (int mt = 0; mt < 4; mt++) {
            const int mA = warpM*64 + mt*16 + mlane;
            #pragma unroll
            for (int nt = 0; nt < 4; nt++) {
                const int nc = warpN*32 + nt*8 + nlane;
                sf[(nc    )*132 + mA    ] = acc[mt][nt][0];
                sf[(nc + 1)*132 + mA    ] = acc[mt][nt][1];
                sf[(nc    )*132 + mA + 8] = acc[mt][nt][2];
                sf[(nc + 1)*132 + mA + 8] = acc[mt][nt][3];
            }
        }
        __syncthreads();
        #pragma unroll 4
        for (int i = tid; i < 128*128; i += 256) {
            const int n = i >> 7, mm = i & 127;
            const int tok = (int)m0 + mm;
            const int b = tok / HWc, pix = tok % HWc;
            Of[((size_t)b*DIM + n0 + n)*HWc + pix] = sf[n*132 + mm] + sbias[n];
        }
    }
}

// ---------------- launch -----------------------------------------------------
extern "C" void kernel_launch(void* const* d_in, const int* in_sizes, int n_in,
                              void* d_out, int out_size)
{
    const float* x      = (const float*)d_in[0];
    const float* conv_w = (const float*)d_in[1];
    const float* conv_b = (const float*)d_in[2];
    const float* ln_g   = (const float*)d_in[3];
    const float* ln_b   = (const float*)d_in[4];
    const float* w1     = (const float*)d_in[5];
    const float* b1     = (const float*)d_in[6];
    const float* w2     = (const float*)d_in[7];
    const float* b2     = (const float*)d_in[8];
    float* out = (float*)d_out;

    f16 *p_a, *p_h, *p_w1t, *p_w2t;
    cudaGetSymbolAddress((void**)&p_a,   g_a);
    cudaGetSymbolAddress((void**)&p_h,   g_h);
    cudaGetSymbolAddress((void**)&p_w1t, g_w1t);
    cudaGetSymbolAddress((void**)&p_w2t, g_w2t);

    cudaFuncSetAttribute((const void*)hgemm_kernel<DIM, 1>,
                         cudaFuncAttributeMaxDynamicSharedMemorySize, GSMEM);
    cudaFuncSetAttribute((const void*)hgemm_kernel<HID, 2>,
                         cudaFuncAttributeMaxDynamicSharedMemorySize, GSMEM);

    // conv (8192 blocks) + fused weight-prep (2048 blocks)
    dwconv_kernel<<<Bc*DIM + (2*HID*DIM)/256, 256>>>(x, conv_w, conv_b, w1, w2);
    ln_kernel<<<TOK/64, 256>>>(ln_g, ln_b);

    // GEMM1: [TOK,256] x w1t -> tanh-GELU -> h (fp16)
    hgemm_kernel<DIM, 1><<<dim3(HID/128, TOK/128), 256, GSMEM>>>(
        p_a, p_w1t, b1, p_h, nullptr);
    // GEMM2: [TOK,1024] x w2t -> +b2 -> fp32 NCHW out
    hgemm_kernel<HID, 2><<<dim3(DIM/128, TOK/128), 256, GSMEM>>>(
        p_h, p_w2t, b2, nullptr, out);
}